// round 1
// baseline (speedup 1.0000x reference)
#include <cuda_runtime.h>
#include <cuda_bf16.h>
#include <math.h>

// Problem constants
#define BATCH 2
#define SEQ   2048
#define DMODEL 1024
#define NHEAD 16
#define DHEAD 64
#define MTOT  (BATCH*SEQ)          // 4096
#define N_QKV (3*DMODEL)           // 3072

// Scratch (allocation-free rule: __device__ globals)
__device__ float g_qkv[(size_t)MTOT * N_QKV];   // [4096, 3072]
__device__ float g_ctx[(size_t)MTOT * DMODEL];  // [4096, 1024]

// ---------------------------------------------------------------------------
// SGEMM: C[M,N] = A[M,K] @ B[K,N] + bias[N]
// BM=128 BN=128 BK=16, 256 threads, 8x8 micro-tile
// ---------------------------------------------------------------------------
__global__ __launch_bounds__(256, 2)
void sgemm_bias_kernel(const float* __restrict__ A, const float* __restrict__ Bm,
                       const float* __restrict__ bias, float* __restrict__ C,
                       int M, int N, int K)
{
    constexpr int BM = 128, BN = 128, BK = 16, TM = 8, TN = 8;
    __shared__ float As[BK][BM + 4];
    __shared__ float Bs[BK][BN];

    const int tid  = threadIdx.x;
    const int tCol = tid & 15;        // 0..15
    const int tRow = tid >> 4;        // 0..15
    const int bN   = blockIdx.x * BN;
    const int bM   = blockIdx.y * BM;

    const int aRow = tid >> 2;        // 0..63
    const int aCol = (tid & 3) * 4;   // 0,4,8,12
    const int bRow = tid >> 5;        // 0..7
    const int bCol = (tid & 31) * 4;  // 0..124

    float acc[TM][TN];
    #pragma unroll
    for (int i = 0; i < TM; i++)
        #pragma unroll
        for (int j = 0; j < TN; j++) acc[i][j] = 0.f;

    for (int k0 = 0; k0 < K; k0 += BK) {
        // Load A tile (transposed into smem)
        #pragma unroll
        for (int t = 0; t < 2; t++) {
            int row = aRow + t * 64;
            float4 v = *(const float4*)(A + (size_t)(bM + row) * K + k0 + aCol);
            As[aCol + 0][row] = v.x;
            As[aCol + 1][row] = v.y;
            As[aCol + 2][row] = v.z;
            As[aCol + 3][row] = v.w;
        }
        // Load B tile
        #pragma unroll
        for (int t = 0; t < 2; t++) {
            int row = bRow + t * 8;
            *(float4*)&Bs[row][bCol] =
                *(const float4*)(Bm + (size_t)(k0 + row) * N + bN + bCol);
        }
        __syncthreads();

        #pragma unroll
        for (int k = 0; k < BK; k++) {
            float af[TM], bf[TN];
            #pragma unroll
            for (int i = 0; i < TM; i += 4)
                *(float4*)&af[i] = *(const float4*)&As[k][tRow * TM + i];
            #pragma unroll
            for (int j = 0; j < TN; j += 4)
                *(float4*)&bf[j] = *(const float4*)&Bs[k][tCol * TN + j];
            #pragma unroll
            for (int i = 0; i < TM; i++)
                #pragma unroll
                for (int j = 0; j < TN; j++)
                    acc[i][j] += af[i] * bf[j];
        }
        __syncthreads();
    }

    // Epilogue: add bias, vectorized store
    #pragma unroll
    for (int i = 0; i < TM; i++) {
        int row = bM + tRow * TM + i;
        #pragma unroll
        for (int j = 0; j < TN; j += 4) {
            int col = bN + tCol * TN + j;
            float4 o;
            o.x = acc[i][j + 0] + bias[col + 0];
            o.y = acc[i][j + 1] + bias[col + 1];
            o.z = acc[i][j + 2] + bias[col + 2];
            o.w = acc[i][j + 3] + bias[col + 3];
            *(float4*)(C + (size_t)row * N + col) = o;
        }
    }
}

// ---------------------------------------------------------------------------
// Flash attention: one CTA per (b, h, 64-row Q tile). 256 threads.
// Thread (r = tid>>2, c4 = tid&3): row r, score columns j = c4 + 4*jj.
// Q row held in registers (shfl broadcast). K/V tiles in padded smem.
// Online softmax, fp32 accumulators, 4-thread cross reduce at the end.
// ---------------------------------------------------------------------------
__global__ __launch_bounds__(256, 2)
void flash_attn_kernel(const float* __restrict__ qkv, float* __restrict__ ctx)
{
    const int qtile = blockIdx.x;   // 0..31
    const int h     = blockIdx.y;   // 0..15
    const int b     = blockIdx.z;   // 0..1

    const int tid  = threadIdx.x;
    const int r    = tid >> 2;      // 0..63  (row in Q tile; also row loaded for K/V)
    const int c4   = tid & 3;       // 0..3
    const int lane = tid & 31;

    __shared__ float Ks[64][68];
    __shared__ float Vs[64][68];

    const int q0 = qtile * 64;
    const float scale = 0.125f;     // 1/sqrt(64)

    // Load my Q row slice (dims c4*16 .. c4*16+15), pre-scaled
    float4 qreg[4];
    {
        const float* qbase =
            qkv + (size_t)(b * SEQ + q0 + r) * N_QKV + h * DHEAD + c4 * 16;
        #pragma unroll
        for (int i = 0; i < 4; i++) {
            float4 v = *(const float4*)(qbase + i * 4);
            v.x *= scale; v.y *= scale; v.z *= scale; v.w *= scale;
            qreg[i] = v;
        }
    }

    float m = -INFINITY, l = 0.f;
    float4 acc4[16];
    #pragma unroll
    for (int i = 0; i < 16; i++) acc4[i] = make_float4(0.f, 0.f, 0.f, 0.f);

    for (int kt = 0; kt < SEQ / 64; kt++) {
        __syncthreads();   // protect previous tile's smem reads
        // Cooperative load of K and V tiles (64x64 each)
        {
            const float* kbase =
                qkv + (size_t)(b * SEQ + kt * 64 + r) * N_QKV + DMODEL + h * DHEAD + c4 * 16;
            const float* vbase = kbase + DMODEL;
            #pragma unroll
            for (int i = 0; i < 4; i++) {
                *(float4*)&Ks[r][c4 * 16 + i * 4] = *(const float4*)(kbase + i * 4);
                *(float4*)&Vs[r][c4 * 16 + i * 4] = *(const float4*)(vbase + i * 4);
            }
        }
        __syncthreads();

        // S = Q K^T for my 16 columns j = c4 + 4*jj
        float s[16];
        #pragma unroll
        for (int jj = 0; jj < 16; jj++) s[jj] = 0.f;

        #pragma unroll
        for (int d4 = 0; d4 < 16; d4++) {
            // broadcast Q dims d4*4..d4*4+3 from owning thread of this row
            const int src = (lane & 28) | (d4 >> 2);
            float4 qs = qreg[d4 & 3];
            float4 qv;
            qv.x = __shfl_sync(0xffffffffu, qs.x, src);
            qv.y = __shfl_sync(0xffffffffu, qs.y, src);
            qv.z = __shfl_sync(0xffffffffu, qs.z, src);
            qv.w = __shfl_sync(0xffffffffu, qs.w, src);
            #pragma unroll
            for (int jj = 0; jj < 16; jj++) {
                const int j = c4 + 4 * jj;
                float4 kv = *(const float4*)&Ks[j][d4 * 4];
                s[jj] += qv.x * kv.x + qv.y * kv.y + qv.z * kv.z + qv.w * kv.w;
            }
        }

        // online softmax
        float mt = s[0];
        #pragma unroll
        for (int jj = 1; jj < 16; jj++) mt = fmaxf(mt, s[jj]);
        mt = fmaxf(mt, __shfl_xor_sync(0xffffffffu, mt, 1));
        mt = fmaxf(mt, __shfl_xor_sync(0xffffffffu, mt, 2));
        const float m_new = fmaxf(m, mt);
        const float corr  = __expf(m - m_new);   // 0 on first tile (m = -inf)
        float ps = 0.f;
        #pragma unroll
        for (int jj = 0; jj < 16; jj++) {
            s[jj] = __expf(s[jj] - m_new);
            ps += s[jj];
        }
        ps += __shfl_xor_sync(0xffffffffu, ps, 1);
        ps += __shfl_xor_sync(0xffffffffu, ps, 2);
        l = l * corr + ps;
        m = m_new;

        // rescale accumulator
        #pragma unroll
        for (int i = 0; i < 16; i++) {
            acc4[i].x *= corr; acc4[i].y *= corr;
            acc4[i].z *= corr; acc4[i].w *= corr;
        }

        // O += P @ V (my 16 j's, all 64 dims)
        #pragma unroll
        for (int jj = 0; jj < 16; jj++) {
            const float p = s[jj];
            const int j = c4 + 4 * jj;
            #pragma unroll
            for (int d4 = 0; d4 < 16; d4++) {
                float4 v = *(const float4*)&Vs[j][d4 * 4];
                acc4[d4].x += p * v.x;
                acc4[d4].y += p * v.y;
                acc4[d4].z += p * v.z;
                acc4[d4].w += p * v.w;
            }
        }
    }

    // cross-thread reduce (4 threads per row), normalize, write
    const float inv = 1.f / l;
    float* ctxbase = ctx + (size_t)(b * SEQ + q0 + r) * DMODEL + h * DHEAD;
    #pragma unroll
    for (int i = 0; i < 16; i++) {
        float4 a = acc4[i];
        a.x += __shfl_xor_sync(0xffffffffu, a.x, 1);
        a.x += __shfl_xor_sync(0xffffffffu, a.x, 2);
        a.y += __shfl_xor_sync(0xffffffffu, a.y, 1);
        a.y += __shfl_xor_sync(0xffffffffu, a.y, 2);
        a.z += __shfl_xor_sync(0xffffffffu, a.z, 1);
        a.z += __shfl_xor_sync(0xffffffffu, a.z, 2);
        a.w += __shfl_xor_sync(0xffffffffu, a.w, 1);
        a.w += __shfl_xor_sync(0xffffffffu, a.w, 2);
        if ((i >> 2) == c4) {
            a.x *= inv; a.y *= inv; a.z *= inv; a.w *= inv;
            *(float4*)(ctxbase + i * 4) = a;
        }
    }
}

// ---------------------------------------------------------------------------
extern "C" void kernel_launch(void* const* d_in, const int* in_sizes, int n_in,
                              void* d_out, int out_size)
{
    const float* x      = (const float*)d_in[0];   // [2,2048,1024]
    const float* w_qkv  = (const float*)d_in[1];   // [1024,3072]
    const float* b_qkv  = (const float*)d_in[2];   // [3072]
    const float* w_out  = (const float*)d_in[3];   // [1024,1024]
    const float* b_out  = (const float*)d_in[4];   // [1024]
    float* out = (float*)d_out;                    // [2,2048,1024]

    float *qkv_ptr = nullptr, *ctx_ptr = nullptr;
    cudaGetSymbolAddress((void**)&qkv_ptr, g_qkv);
    cudaGetSymbolAddress((void**)&ctx_ptr, g_ctx);

    // 1) QKV projection: [4096,1024] @ [1024,3072] + bias
    {
        dim3 grid(N_QKV / 128, MTOT / 128);
        sgemm_bias_kernel<<<grid, 256>>>(x, w_qkv, b_qkv, qkv_ptr,
                                         MTOT, N_QKV, DMODEL);
    }
    // 2) Flash attention -> context [4096,1024]
    {
        dim3 grid(SEQ / 64, NHEAD, BATCH);
        flash_attn_kernel<<<grid, 256>>>(qkv_ptr, ctx_ptr);
    }
    // 3) Output projection: [4096,1024] @ [1024,1024] + bias
    {
        dim3 grid(DMODEL / 128, MTOT / 128);
        sgemm_bias_kernel<<<grid, 256>>>(ctx_ptr, w_out, b_out, out,
                                         MTOT, DMODEL, DMODEL);
    }
}

// round 2
// speedup vs baseline: 1.5161x; 1.5161x over previous
#include <cuda_runtime.h>
#include <math.h>

#define BATCH 2
#define SEQ   2048
#define DMODEL 1024
#define NHEAD 16
#define DHEAD 64
#define MTOT  (BATCH*SEQ)          // 4096
#define N_QKV (3*DMODEL)           // 3072

__device__ float g_qkv[(size_t)MTOT * N_QKV];   // [4096, 3072]
__device__ float g_ctx[(size_t)MTOT * DMODEL];  // [4096, 1024]

// ---------------------------------------------------------------------------
// SGEMM with double-buffered smem: C[M,N] = A[M,K] @ B[K,N] + bias[N]
// BM=128 BN=128 BK=16, 256 threads, 8x8 micro-tile
// ---------------------------------------------------------------------------
__global__ __launch_bounds__(256, 2)
void sgemm_bias_kernel(const float* __restrict__ A, const float* __restrict__ Bm,
                       const float* __restrict__ bias, float* __restrict__ C,
                       int M, int N, int K)
{
    constexpr int BM = 128, BN = 128, BK = 16, TM = 8, TN = 8;
    __shared__ float As[2][BK][BM + 4];
    __shared__ float Bs[2][BK][BN];

    const int tid  = threadIdx.x;
    const int tCol = tid & 15;
    const int tRow = tid >> 4;
    const int bN   = blockIdx.x * BN;
    const int bM   = blockIdx.y * BM;

    const int aRow = tid >> 2;        // 0..63
    const int aCol = (tid & 3) * 4;   // 0,4,8,12
    const int bRow = tid >> 5;        // 0..7
    const int bCol = (tid & 31) * 4;  // 0..124

    float acc[TM][TN];
    #pragma unroll
    for (int i = 0; i < TM; i++)
        #pragma unroll
        for (int j = 0; j < TN; j++) acc[i][j] = 0.f;

    const int NT = K / BK;

    float4 apre0, apre1, bpre0, bpre1;

    // preload tile 0
    apre0 = *(const float4*)(A + (size_t)(bM + aRow)      * K + aCol);
    apre1 = *(const float4*)(A + (size_t)(bM + aRow + 64) * K + aCol);
    bpre0 = *(const float4*)(Bm + (size_t)(bRow)     * N + bN + bCol);
    bpre1 = *(const float4*)(Bm + (size_t)(bRow + 8) * N + bN + bCol);
    {
        As[0][aCol + 0][aRow] = apre0.x;  As[0][aCol + 1][aRow] = apre0.y;
        As[0][aCol + 2][aRow] = apre0.z;  As[0][aCol + 3][aRow] = apre0.w;
        As[0][aCol + 0][aRow + 64] = apre1.x;  As[0][aCol + 1][aRow + 64] = apre1.y;
        As[0][aCol + 2][aRow + 64] = apre1.z;  As[0][aCol + 3][aRow + 64] = apre1.w;
        *(float4*)&Bs[0][bRow][bCol]     = bpre0;
        *(float4*)&Bs[0][bRow + 8][bCol] = bpre1;
    }
    __syncthreads();

    for (int t = 0; t < NT; t++) {
        const int cur = t & 1, nxt = cur ^ 1;
        if (t + 1 < NT) {
            const int k0 = (t + 1) * BK;
            apre0 = *(const float4*)(A + (size_t)(bM + aRow)      * K + k0 + aCol);
            apre1 = *(const float4*)(A + (size_t)(bM + aRow + 64) * K + k0 + aCol);
            bpre0 = *(const float4*)(Bm + (size_t)(k0 + bRow)     * N + bN + bCol);
            bpre1 = *(const float4*)(Bm + (size_t)(k0 + bRow + 8) * N + bN + bCol);
        }

        #pragma unroll
        for (int k = 0; k < BK; k++) {
            float af[TM], bf[TN];
            #pragma unroll
            for (int i = 0; i < TM; i += 4)
                *(float4*)&af[i] = *(const float4*)&As[cur][k][tRow * TM + i];
            #pragma unroll
            for (int j = 0; j < TN; j += 4)
                *(float4*)&bf[j] = *(const float4*)&Bs[cur][k][tCol * TN + j];
            #pragma unroll
            for (int i = 0; i < TM; i++)
                #pragma unroll
                for (int j = 0; j < TN; j++)
                    acc[i][j] += af[i] * bf[j];
        }

        if (t + 1 < NT) {
            As[nxt][aCol + 0][aRow] = apre0.x;  As[nxt][aCol + 1][aRow] = apre0.y;
            As[nxt][aCol + 2][aRow] = apre0.z;  As[nxt][aCol + 3][aRow] = apre0.w;
            As[nxt][aCol + 0][aRow + 64] = apre1.x;  As[nxt][aCol + 1][aRow + 64] = apre1.y;
            As[nxt][aCol + 2][aRow + 64] = apre1.z;  As[nxt][aCol + 3][aRow + 64] = apre1.w;
            *(float4*)&Bs[nxt][bRow][bCol]     = bpre0;
            *(float4*)&Bs[nxt][bRow + 8][bCol] = bpre1;
            __syncthreads();
        }
    }

    #pragma unroll
    for (int i = 0; i < TM; i++) {
        int row = bM + tRow * TM + i;
        #pragma unroll
        for (int j = 0; j < TN; j += 4) {
            int col = bN + tCol * TN + j;
            float4 o;
            o.x = acc[i][j + 0] + bias[col + 0];
            o.y = acc[i][j + 1] + bias[col + 1];
            o.z = acc[i][j + 2] + bias[col + 2];
            o.w = acc[i][j + 3] + bias[col + 3];
            *(float4*)(C + (size_t)row * N + col) = o;
        }
    }
}

// ---------------------------------------------------------------------------
// Flash attention, GEMM-tiled. One CTA per (b, h, 128-row Q tile), 256 threads.
// QK^T: 8x8 micro-tile (16x16 thread grid). P staged in smem. PV: 8 rows x 4 dims.
// Dynamic smem ~175KB, 1 CTA/SM.
// ---------------------------------------------------------------------------
__global__ __launch_bounds__(256, 1)
void flash_attn_kernel(const float* __restrict__ qkv, float* __restrict__ ctx)
{
    extern __shared__ float sm[];
    float* Qs      = sm;                   // [64][132]  Qs[d][qrow]
    float* Ks      = Qs + 64 * 132;        // [64][128]  Ks[d][kcol]
    float* Vs      = Ks + 64 * 128;        // [128][68]  Vs[j][d]
    float* Ps      = Vs + 128 * 68;        // [128][132] Ps[qrow][j]
    float* red     = Ps + 128 * 132;       // [128][17]
    float* rowm    = red + 128 * 17;       // [128]
    float* rowl    = rowm + 128;           // [128]
    float* rowcorr = rowl + 128;           // [128]

    const int qt  = blockIdx.x;            // 0..15
    const int h   = blockIdx.y;            // 0..15
    const int b   = blockIdx.z;            // 0..1
    const int tid = threadIdx.x;
    const int tCol = tid & 15;
    const int tRow = tid >> 4;
    const int q0  = qt * 128;

    const int r2   = tid >> 1;             // 0..127
    const int dseg = (tid & 1) * 32;       // 0 or 32

    // Load Q tile (pre-scaled by 1/sqrt(64)), transposed into Qs[d][row]
    {
        const float* qb = qkv + (size_t)(b * SEQ + q0 + r2) * N_QKV + h * DHEAD + dseg;
        #pragma unroll
        for (int i = 0; i < 8; i++) {
            float4 v = *(const float4*)(qb + i * 4);
            int d = dseg + i * 4;
            Qs[(d + 0) * 132 + r2] = v.x * 0.125f;
            Qs[(d + 1) * 132 + r2] = v.y * 0.125f;
            Qs[(d + 2) * 132 + r2] = v.z * 0.125f;
            Qs[(d + 3) * 132 + r2] = v.w * 0.125f;
        }
    }
    if (tid < 128) { rowm[tid] = -INFINITY; rowl[tid] = 0.f; }

    float4 acc_o[8];
    #pragma unroll
    for (int i = 0; i < 8; i++) acc_o[i] = make_float4(0.f, 0.f, 0.f, 0.f);

    for (int kt = 0; kt < SEQ / 128; kt++) {
        __syncthreads();   // protect Ks/Vs/Ps/red from previous iteration readers
        // Load K (transposed) and V tiles
        {
            const float* kb = qkv + (size_t)(b * SEQ + kt * 128 + r2) * N_QKV
                              + DMODEL + h * DHEAD + dseg;
            const float* vb = kb + DMODEL;
            #pragma unroll
            for (int i = 0; i < 8; i++) {
                float4 kv = *(const float4*)(kb + i * 4);
                int d = dseg + i * 4;
                Ks[(d + 0) * 128 + r2] = kv.x;
                Ks[(d + 1) * 128 + r2] = kv.y;
                Ks[(d + 2) * 128 + r2] = kv.z;
                Ks[(d + 3) * 128 + r2] = kv.w;
                *(float4*)&Vs[r2 * 68 + d] = *(const float4*)(vb + i * 4);
            }
        }
        __syncthreads();

        // S = Q K^T (scaled Q), 8x8 per thread
        float s[8][8];
        #pragma unroll
        for (int i = 0; i < 8; i++)
            #pragma unroll
            for (int j = 0; j < 8; j++) s[i][j] = 0.f;

        #pragma unroll 4
        for (int d = 0; d < 64; d++) {
            float af[8], bf[8];
            *(float4*)&af[0] = *(const float4*)&Qs[d * 132 + tRow * 8];
            *(float4*)&af[4] = *(const float4*)&Qs[d * 132 + tRow * 8 + 4];
            *(float4*)&bf[0] = *(const float4*)&Ks[d * 128 + tCol * 8];
            *(float4*)&bf[4] = *(const float4*)&Ks[d * 128 + tCol * 8 + 4];
            #pragma unroll
            for (int i = 0; i < 8; i++)
                #pragma unroll
                for (int j = 0; j < 8; j++)
                    s[i][j] += af[i] * bf[j];
        }

        // Row partial max
        #pragma unroll
        for (int i = 0; i < 8; i++) {
            float mx = s[i][0];
            #pragma unroll
            for (int j = 1; j < 8; j++) mx = fmaxf(mx, s[i][j]);
            red[(tRow * 8 + i) * 17 + tCol] = mx;
        }
        __syncthreads();
        if (tid < 128) {
            float mt = red[tid * 17];
            #pragma unroll
            for (int k = 1; k < 16; k++) mt = fmaxf(mt, red[tid * 17 + k]);
            float m_old = rowm[tid];
            float m_new = fmaxf(m_old, mt);
            rowcorr[tid] = __expf(m_old - m_new);   // 0 on first tile
            rowm[tid] = m_new;
        }
        __syncthreads();

        // exp, write P to smem, row partial sums
        #pragma unroll
        for (int i = 0; i < 8; i++) {
            const int row = tRow * 8 + i;
            const float mr = rowm[row];
            float sum = 0.f;
            #pragma unroll
            for (int j = 0; j < 8; j++) {
                float e = __expf(s[i][j] - mr);
                s[i][j] = e;
                sum += e;
            }
            red[row * 17 + tCol] = sum;
            *(float4*)&Ps[row * 132 + tCol * 8]     = make_float4(s[i][0], s[i][1], s[i][2], s[i][3]);
            *(float4*)&Ps[row * 132 + tCol * 8 + 4] = make_float4(s[i][4], s[i][5], s[i][6], s[i][7]);
        }
        __syncthreads();
        if (tid < 128) {
            float sum = 0.f;
            #pragma unroll
            for (int k = 0; k < 16; k++) sum += red[tid * 17 + k];
            rowl[tid] = rowl[tid] * rowcorr[tid] + sum;
        }

        // Rescale O accumulator
        #pragma unroll
        for (int i = 0; i < 8; i++) {
            float c = rowcorr[tRow * 8 + i];
            acc_o[i].x *= c; acc_o[i].y *= c; acc_o[i].z *= c; acc_o[i].w *= c;
        }

        // O += P @ V : thread owns 8 rows x 4 dims (dims = tCol*4..+3)
        #pragma unroll 2
        for (int j4 = 0; j4 < 32; j4++) {
            float4 v0 = *(const float4*)&Vs[(j4 * 4 + 0) * 68 + tCol * 4];
            float4 v1 = *(const float4*)&Vs[(j4 * 4 + 1) * 68 + tCol * 4];
            float4 v2 = *(const float4*)&Vs[(j4 * 4 + 2) * 68 + tCol * 4];
            float4 v3 = *(const float4*)&Vs[(j4 * 4 + 3) * 68 + tCol * 4];
            #pragma unroll
            for (int i = 0; i < 8; i++) {
                float4 p = *(const float4*)&Ps[(tRow * 8 + i) * 132 + j4 * 4];
                acc_o[i].x += p.x * v0.x + p.y * v1.x + p.z * v2.x + p.w * v3.x;
                acc_o[i].y += p.x * v0.y + p.y * v1.y + p.z * v2.y + p.w * v3.y;
                acc_o[i].z += p.x * v0.z + p.y * v1.z + p.z * v2.z + p.w * v3.z;
                acc_o[i].w += p.x * v0.w + p.y * v1.w + p.z * v2.w + p.w * v3.w;
            }
        }
    }

    __syncthreads();   // rowl final values visible to all threads

    #pragma unroll
    for (int i = 0; i < 8; i++) {
        const int row = tRow * 8 + i;
        const float inv = 1.f / rowl[row];
        float4 o = acc_o[i];
        o.x *= inv; o.y *= inv; o.z *= inv; o.w *= inv;
        *(float4*)(ctx + (size_t)(b * SEQ + q0 + row) * DMODEL + h * DHEAD + tCol * 4) = o;
    }
}

// ---------------------------------------------------------------------------
extern "C" void kernel_launch(void* const* d_in, const int* in_sizes, int n_in,
                              void* d_out, int out_size)
{
    const float* x      = (const float*)d_in[0];
    const float* w_qkv  = (const float*)d_in[1];
    const float* b_qkv  = (const float*)d_in[2];
    const float* w_out  = (const float*)d_in[3];
    const float* b_out  = (const float*)d_in[4];
    float* out = (float*)d_out;

    float *qkv_ptr = nullptr, *ctx_ptr = nullptr;
    cudaGetSymbolAddress((void**)&qkv_ptr, g_qkv);
    cudaGetSymbolAddress((void**)&ctx_ptr, g_ctx);

    const int FLASH_SMEM = (64*132 + 64*128 + 128*68 + 128*132 + 128*17 + 3*128) * 4;
    cudaFuncSetAttribute(flash_attn_kernel,
                         cudaFuncAttributeMaxDynamicSharedMemorySize, FLASH_SMEM);

    // 1) QKV projection
    {
        dim3 grid(N_QKV / 128, MTOT / 128);
        sgemm_bias_kernel<<<grid, 256>>>(x, w_qkv, b_qkv, qkv_ptr,
                                         MTOT, N_QKV, DMODEL);
    }
    // 2) Flash attention
    {
        dim3 grid(SEQ / 128, NHEAD, BATCH);
        flash_attn_kernel<<<grid, 256, FLASH_SMEM>>>(qkv_ptr, ctx_ptr);
    }
    // 3) Output projection
    {
        dim3 grid(DMODEL / 128, MTOT / 128);
        sgemm_bias_kernel<<<grid, 256>>>(ctx_ptr, w_out, b_out, out,
                                         MTOT, DMODEL, DMODEL);
    }
}

// round 4
// speedup vs baseline: 2.0847x; 1.3750x over previous
#include <cuda_runtime.h>
#include <cuda_bf16.h>
#include <math.h>
#include <stdint.h>

#define BATCH 2
#define SEQ   2048
#define DMODEL 1024
#define NHEAD 16
#define DHEAD 64
#define MTOT  (BATCH*SEQ)          // 4096
#define N_QKV (3*DMODEL)           // 3072

// ---------------------------------------------------------------------------
// Scratch (__device__ globals; allocation-free rule)
// ---------------------------------------------------------------------------
__device__ float g_qkv[(size_t)MTOT * N_QKV];
__device__ __nv_bfloat16 g_xh[(size_t)MTOT * DMODEL];
__device__ __nv_bfloat16 g_xl[(size_t)MTOT * DMODEL];
__device__ __nv_bfloat16 g_wqkvT_h[(size_t)N_QKV * DMODEL];   // [N][K]
__device__ __nv_bfloat16 g_wqkvT_l[(size_t)N_QKV * DMODEL];
__device__ __nv_bfloat16 g_woutT_h[(size_t)DMODEL * DMODEL];
__device__ __nv_bfloat16 g_woutT_l[(size_t)DMODEL * DMODEL];
__device__ __nv_bfloat16 g_ctxh[(size_t)MTOT * DMODEL];
__device__ __nv_bfloat16 g_ctxl[(size_t)MTOT * DMODEL];

// ---------------------------------------------------------------------------
// Helpers (sm_80+ portable: ldmatrix / mma.sync / cp.async)
// ---------------------------------------------------------------------------
__device__ __forceinline__ uint32_t smem_to_u32(const void* p) {
    uint32_t a;
    asm("{ .reg .u64 t; cvta.to.shared.u64 t, %1; cvt.u32.u64 %0, t; }" : "=r"(a) : "l"(p));
    return a;
}
__device__ __forceinline__ void ldsm_x4(uint32_t& r0, uint32_t& r1, uint32_t& r2,
                                        uint32_t& r3, uint32_t addr) {
    asm volatile("ldmatrix.sync.aligned.m8n8.x4.shared.b16 {%0,%1,%2,%3}, [%4];"
                 : "=r"(r0), "=r"(r1), "=r"(r2), "=r"(r3) : "r"(addr));
}
__device__ __forceinline__ void mma_bf16(float* c, const uint32_t* a, const uint32_t* b) {
    asm volatile(
        "mma.sync.aligned.m16n8k16.row.col.f32.bf16.bf16.f32 "
        "{%0,%1,%2,%3}, {%4,%5,%6,%7}, {%8,%9}, {%0,%1,%2,%3};"
        : "+f"(c[0]), "+f"(c[1]), "+f"(c[2]), "+f"(c[3])
        : "r"(a[0]), "r"(a[1]), "r"(a[2]), "r"(a[3]), "r"(b[0]), "r"(b[1]));
}
__device__ __forceinline__ void cp_async16(uint32_t saddr, const void* gaddr) {
    asm volatile("cp.async.cg.shared.global [%0], [%1], 16;" :: "r"(saddr), "l"(gaddr));
}
#define CP_COMMIT() asm volatile("cp.async.commit_group;" ::: "memory")

// ---------------------------------------------------------------------------
// fp32 -> (hi, lo) bf16 split (for x)
// ---------------------------------------------------------------------------
__global__ void convert_split_kernel(const float* __restrict__ in,
                                     __nv_bfloat16* __restrict__ oh,
                                     __nv_bfloat16* __restrict__ ol, int n4)
{
    for (int i = blockIdx.x * blockDim.x + threadIdx.x; i < n4; i += gridDim.x * blockDim.x) {
        float4 v = *(const float4*)(in + (size_t)i * 4);
        __nv_bfloat16 h0 = __float2bfloat16_rn(v.x), h1 = __float2bfloat16_rn(v.y);
        __nv_bfloat16 h2 = __float2bfloat16_rn(v.z), h3 = __float2bfloat16_rn(v.w);
        __nv_bfloat16 l0 = __float2bfloat16_rn(v.x - __bfloat162float(h0));
        __nv_bfloat16 l1 = __float2bfloat16_rn(v.y - __bfloat162float(h1));
        __nv_bfloat16 l2 = __float2bfloat16_rn(v.z - __bfloat162float(h2));
        __nv_bfloat16 l3 = __float2bfloat16_rn(v.w - __bfloat162float(h3));
        __nv_bfloat162* ph = (__nv_bfloat162*)(oh + (size_t)i * 4);
        __nv_bfloat162* pl = (__nv_bfloat162*)(ol + (size_t)i * 4);
        ph[0] = __nv_bfloat162(h0, h1); ph[1] = __nv_bfloat162(h2, h3);
        pl[0] = __nv_bfloat162(l0, l1); pl[1] = __nv_bfloat162(l2, l3);
    }
}

// ---------------------------------------------------------------------------
// w[K][N] fp32 -> wT hi/lo [N][K] bf16
// ---------------------------------------------------------------------------
__global__ void transpose_split_kernel(const float* __restrict__ w,
                                       __nv_bfloat16* __restrict__ th,
                                       __nv_bfloat16* __restrict__ tl,
                                       int K, int N)
{
    __shared__ float tile[32][33];
    const int tx = threadIdx.x, ty = threadIdx.y;
    const int x0 = blockIdx.x * 32;   // N
    const int y0 = blockIdx.y * 32;   // K
    #pragma unroll
    for (int i = 0; i < 4; i++) {
        int kl = ty + i * 8;
        tile[kl][tx] = w[(size_t)(y0 + kl) * N + x0 + tx];
    }
    __syncthreads();
    #pragma unroll
    for (int i = 0; i < 4; i++) {
        int nl = ty + i * 8;
        float v = tile[tx][nl];
        __nv_bfloat16 h = __float2bfloat16_rn(v);
        __nv_bfloat16 l = __float2bfloat16_rn(v - __bfloat162float(h));
        th[(size_t)(x0 + nl) * K + y0 + tx] = h;
        tl[(size_t)(x0 + nl) * K + y0 + tx] = l;
    }
}

// ---------------------------------------------------------------------------
// bf16-split tensor GEMM via mma.sync: C[M,N] = A@B^T + bias
// A = [M,K] hi/lo bf16, B = [N,K] hi/lo bf16 (both K-major).
// CTA 128x128, BK=32, 8 warps (2x4), warp tile 64x32, double-buffered cp.async.
// smem rows padded to 80B (stride 40 bf16) -> conflict-free ldmatrix.
// ---------------------------------------------------------------------------
#define TILE_B   (128 * 80)         // bytes per operand tile (padded)
#define STAGE_B  (4 * TILE_B)       // Ah, Al, Bh, Bl

__global__ __launch_bounds__(256)
void gemm_mma_kernel(const __nv_bfloat16* __restrict__ Ah, const __nv_bfloat16* __restrict__ Al,
                     const __nv_bfloat16* __restrict__ Bh, const __nv_bfloat16* __restrict__ Bl,
                     const float* __restrict__ bias, float* __restrict__ C,
                     int M, int N, int K)
{
    extern __shared__ __align__(16) char smem[];
    const uint32_t sbase = smem_to_u32(smem);

    const int tid = threadIdx.x;
    const int lane = tid & 31;
    const int wid = tid >> 5;
    const int warp_m = wid >> 2;       // 0..1
    const int warp_n = wid & 3;        // 0..3
    const int bM = blockIdx.y * 128, bN = blockIdx.x * 128;

    // g2s mapping: row = tid>>2 (+64), slot = tid&3 (16B each, 64B per row)
    const int grow = tid >> 2;
    const int gslot = tid & 3;

    const int NT = K / 32;

    // ---- issue stage t ----
    auto issue = [&](int t) {
        const uint32_t sb = sbase + (t & 1) * STAGE_B;
        const int kof = t * 32 + gslot * 8;
        #pragma unroll
        for (int p = 0; p < 2; p++) {
            const int r = grow + p * 64;
            const uint32_t so = (uint32_t)(r * 80 + gslot * 16);
            cp_async16(sb + so,              Ah + (size_t)(bM + r) * K + kof);
            cp_async16(sb + TILE_B + so,     Al + (size_t)(bM + r) * K + kof);
            cp_async16(sb + 2 * TILE_B + so, Bh + (size_t)(bN + r) * K + kof);
            cp_async16(sb + 3 * TILE_B + so, Bl + (size_t)(bN + r) * K + kof);
        }
        CP_COMMIT();
    };

    float acc[4][4][4];
    #pragma unroll
    for (int i = 0; i < 4; i++)
        #pragma unroll
        for (int j = 0; j < 4; j++)
            #pragma unroll
            for (int k = 0; k < 4; k++) acc[i][j][k] = 0.f;

    issue(0);

    // ldmatrix lane address components
    const int a_row = (lane & 7) + ((lane >> 3) & 1) * 8;   // within m16 tile
    const int a_sel = (lane >> 4);                           // k half (16B)
    const int b_row = (lane & 7) + ((lane >> 4) << 3);       // within n16 pair
    const int b_sel = (lane >> 3) & 1;                       // k half (16B)

    for (int t = 0; t < NT; t++) {
        if (t + 1 < NT) issue(t + 1);
        if (t + 1 < NT) asm volatile("cp.async.wait_group 1;" ::: "memory");
        else            asm volatile("cp.async.wait_group 0;" ::: "memory");
        __syncthreads();

        const uint32_t sb   = sbase + (t & 1) * STAGE_B;
        const uint32_t sAh = sb, sAl = sb + TILE_B, sBh = sb + 2 * TILE_B, sBl = sb + 3 * TILE_B;

        #pragma unroll
        for (int kk = 0; kk < 2; kk++) {
            // B fragments: 4 n8 tiles, hi and lo (two x4 loads each)
            uint32_t bh[8], bl[8];
            {
                const uint32_t ba = (uint32_t)((warp_n * 32 + b_row) * 80 + kk * 32 + b_sel * 16);
                ldsm_x4(bh[0], bh[1], bh[2], bh[3], sBh + ba);
                ldsm_x4(bh[4], bh[5], bh[6], bh[7], sBh + ba + 16 * 80);
                ldsm_x4(bl[0], bl[1], bl[2], bl[3], sBl + ba);
                ldsm_x4(bl[4], bl[5], bl[6], bl[7], sBl + ba + 16 * 80);
            }
            #pragma unroll
            for (int mt = 0; mt < 4; mt++) {
                const uint32_t aa = (uint32_t)((warp_m * 64 + mt * 16 + a_row) * 80
                                               + kk * 32 + a_sel * 16);
                uint32_t ah[4], al[4];
                ldsm_x4(ah[0], ah[1], ah[2], ah[3], sAh + aa);
                ldsm_x4(al[0], al[1], al[2], al[3], sAl + aa);
                #pragma unroll
                for (int nt = 0; nt < 4; nt++) {
                    mma_bf16(acc[mt][nt], ah, &bh[nt * 2]);
                    mma_bf16(acc[mt][nt], ah, &bl[nt * 2]);
                    mma_bf16(acc[mt][nt], al, &bh[nt * 2]);
                }
            }
        }
        __syncthreads();
    }

    // Epilogue: fragment (mt,nt): rows r0 = ..+lane>>2, r0+8; cols c0 = ..+(lane&3)*2
    #pragma unroll
    for (int mt = 0; mt < 4; mt++) {
        const int r0 = bM + warp_m * 64 + mt * 16 + (lane >> 2);
        #pragma unroll
        for (int nt = 0; nt < 4; nt++) {
            const int c = bN + warp_n * 32 + nt * 8 + (lane & 3) * 2;
            const float bx = bias[c], by = bias[c + 1];
            float2 v0 = make_float2(acc[mt][nt][0] + bx, acc[mt][nt][1] + by);
            float2 v1 = make_float2(acc[mt][nt][2] + bx, acc[mt][nt][3] + by);
            *(float2*)(C + (size_t)r0 * N + c)       = v0;
            *(float2*)(C + (size_t)(r0 + 8) * N + c) = v1;
        }
    }
}

// ---------------------------------------------------------------------------
// Flash attention (fp32 SIMT, proven R2 structure), epilogue -> bf16 hi/lo ctx
// ---------------------------------------------------------------------------
__global__ __launch_bounds__(256, 1)
void flash_attn_kernel(const float* __restrict__ qkv,
                       __nv_bfloat16* __restrict__ ctxh,
                       __nv_bfloat16* __restrict__ ctxl)
{
    extern __shared__ float sm[];
    float* Qs      = sm;                   // [64][132]
    float* Ks      = Qs + 64 * 132;        // [64][128]
    float* Vs      = Ks + 64 * 128;        // [128][68]
    float* Ps      = Vs + 128 * 68;        // [128][132]
    float* red     = Ps + 128 * 132;       // [128][17]
    float* rowm    = red + 128 * 17;
    float* rowl    = rowm + 128;
    float* rowcorr = rowl + 128;

    const int qt  = blockIdx.x;
    const int h   = blockIdx.y;
    const int b   = blockIdx.z;
    const int tid = threadIdx.x;
    const int tCol = tid & 15;
    const int tRow = tid >> 4;
    const int q0  = qt * 128;

    const int r2   = tid >> 1;
    const int dseg = (tid & 1) * 32;

    {
        const float* qb = qkv + (size_t)(b * SEQ + q0 + r2) * N_QKV + h * DHEAD + dseg;
        #pragma unroll
        for (int i = 0; i < 8; i++) {
            float4 v = *(const float4*)(qb + i * 4);
            int d = dseg + i * 4;
            Qs[(d + 0) * 132 + r2] = v.x * 0.125f;
            Qs[(d + 1) * 132 + r2] = v.y * 0.125f;
            Qs[(d + 2) * 132 + r2] = v.z * 0.125f;
            Qs[(d + 3) * 132 + r2] = v.w * 0.125f;
        }
    }
    if (tid < 128) { rowm[tid] = -INFINITY; rowl[tid] = 0.f; }

    float4 acc_o[8];
    #pragma unroll
    for (int i = 0; i < 8; i++) acc_o[i] = make_float4(0.f, 0.f, 0.f, 0.f);

    for (int kt = 0; kt < SEQ / 128; kt++) {
        __syncthreads();
        {
            const float* kb = qkv + (size_t)(b * SEQ + kt * 128 + r2) * N_QKV
                              + DMODEL + h * DHEAD + dseg;
            const float* vb = kb + DMODEL;
            #pragma unroll
            for (int i = 0; i < 8; i++) {
                float4 kv = *(const float4*)(kb + i * 4);
                int d = dseg + i * 4;
                Ks[(d + 0) * 128 + r2] = kv.x;
                Ks[(d + 1) * 128 + r2] = kv.y;
                Ks[(d + 2) * 128 + r2] = kv.z;
                Ks[(d + 3) * 128 + r2] = kv.w;
                *(float4*)&Vs[r2 * 68 + d] = *(const float4*)(vb + i * 4);
            }
        }
        __syncthreads();

        float s[8][8];
        #pragma unroll
        for (int i = 0; i < 8; i++)
            #pragma unroll
            for (int j = 0; j < 8; j++) s[i][j] = 0.f;

        #pragma unroll 4
        for (int d = 0; d < 64; d++) {
            float af[8], bf[8];
            *(float4*)&af[0] = *(const float4*)&Qs[d * 132 + tRow * 8];
            *(float4*)&af[4] = *(const float4*)&Qs[d * 132 + tRow * 8 + 4];
            *(float4*)&bf[0] = *(const float4*)&Ks[d * 128 + tCol * 8];
            *(float4*)&bf[4] = *(const float4*)&Ks[d * 128 + tCol * 8 + 4];
            #pragma unroll
            for (int i = 0; i < 8; i++)
                #pragma unroll
                for (int j = 0; j < 8; j++)
                    s[i][j] += af[i] * bf[j];
        }

        #pragma unroll
        for (int i = 0; i < 8; i++) {
            float mx = s[i][0];
            #pragma unroll
            for (int j = 1; j < 8; j++) mx = fmaxf(mx, s[i][j]);
            red[(tRow * 8 + i) * 17 + tCol] = mx;
        }
        __syncthreads();
        if (tid < 128) {
            float mt = red[tid * 17];
            #pragma unroll
            for (int k = 1; k < 16; k++) mt = fmaxf(mt, red[tid * 17 + k]);
            float m_old = rowm[tid];
            float m_new = fmaxf(m_old, mt);
            rowcorr[tid] = __expf(m_old - m_new);
            rowm[tid] = m_new;
        }
        __syncthreads();

        #pragma unroll
        for (int i = 0; i < 8; i++) {
            const int row = tRow * 8 + i;
            const float mr = rowm[row];
            float sum = 0.f;
            #pragma unroll
            for (int j = 0; j < 8; j++) {
                float e = __expf(s[i][j] - mr);
                s[i][j] = e;
                sum += e;
            }
            red[row * 17 + tCol] = sum;
            *(float4*)&Ps[row * 132 + tCol * 8]     = make_float4(s[i][0], s[i][1], s[i][2], s[i][3]);
            *(float4*)&Ps[row * 132 + tCol * 8 + 4] = make_float4(s[i][4], s[i][5], s[i][6], s[i][7]);
        }
        __syncthreads();
        if (tid < 128) {
            float sum = 0.f;
            #pragma unroll
            for (int k = 0; k < 16; k++) sum += red[tid * 17 + k];
            rowl[tid] = rowl[tid] * rowcorr[tid] + sum;
        }

        #pragma unroll
        for (int i = 0; i < 8; i++) {
            float c = rowcorr[tRow * 8 + i];
            acc_o[i].x *= c; acc_o[i].y *= c; acc_o[i].z *= c; acc_o[i].w *= c;
        }

        #pragma unroll 2
        for (int j4 = 0; j4 < 32; j4++) {
            float4 v0 = *(const float4*)&Vs[(j4 * 4 + 0) * 68 + tCol * 4];
            float4 v1 = *(const float4*)&Vs[(j4 * 4 + 1) * 68 + tCol * 4];
            float4 v2 = *(const float4*)&Vs[(j4 * 4 + 2) * 68 + tCol * 4];
            float4 v3 = *(const float4*)&Vs[(j4 * 4 + 3) * 68 + tCol * 4];
            #pragma unroll
            for (int i = 0; i < 8; i++) {
                float4 p = *(const float4*)&Ps[(tRow * 8 + i) * 132 + j4 * 4];
                acc_o[i].x += p.x * v0.x + p.y * v1.x + p.z * v2.x + p.w * v3.x;
                acc_o[i].y += p.x * v0.y + p.y * v1.y + p.z * v2.y + p.w * v3.y;
                acc_o[i].z += p.x * v0.z + p.y * v1.z + p.z * v2.z + p.w * v3.z;
                acc_o[i].w += p.x * v0.w + p.y * v1.w + p.z * v2.w + p.w * v3.w;
            }
        }
    }

    __syncthreads();

    #pragma unroll
    for (int i = 0; i < 8; i++) {
        const int row = tRow * 8 + i;
        const float inv = 1.f / rowl[row];
        float4 o = acc_o[i];
        o.x *= inv; o.y *= inv; o.z *= inv; o.w *= inv;
        const size_t off = (size_t)(b * SEQ + q0 + row) * DMODEL + h * DHEAD + tCol * 4;
        __nv_bfloat16 h0 = __float2bfloat16_rn(o.x), h1 = __float2bfloat16_rn(o.y);
        __nv_bfloat16 h2 = __float2bfloat16_rn(o.z), h3 = __float2bfloat16_rn(o.w);
        __nv_bfloat16 l0 = __float2bfloat16_rn(o.x - __bfloat162float(h0));
        __nv_bfloat16 l1 = __float2bfloat16_rn(o.y - __bfloat162float(h1));
        __nv_bfloat16 l2 = __float2bfloat16_rn(o.z - __bfloat162float(h2));
        __nv_bfloat16 l3 = __float2bfloat16_rn(o.w - __bfloat162float(h3));
        *(__nv_bfloat162*)(ctxh + off)     = __nv_bfloat162(h0, h1);
        *(__nv_bfloat162*)(ctxh + off + 2) = __nv_bfloat162(h2, h3);
        *(__nv_bfloat162*)(ctxl + off)     = __nv_bfloat162(l0, l1);
        *(__nv_bfloat162*)(ctxl + off + 2) = __nv_bfloat162(l2, l3);
    }
}

// ---------------------------------------------------------------------------
extern "C" void kernel_launch(void* const* d_in, const int* in_sizes, int n_in,
                              void* d_out, int out_size)
{
    const float* x      = (const float*)d_in[0];
    const float* w_qkv  = (const float*)d_in[1];
    const float* b_qkv  = (const float*)d_in[2];
    const float* w_out  = (const float*)d_in[3];
    const float* b_out  = (const float*)d_in[4];
    float* out = (float*)d_out;

    float* qkv_ptr = nullptr;
    __nv_bfloat16 *xh, *xl, *wqh, *wql, *woh, *wol, *ch, *cl;
    cudaGetSymbolAddress((void**)&qkv_ptr, g_qkv);
    cudaGetSymbolAddress((void**)&xh, g_xh);
    cudaGetSymbolAddress((void**)&xl, g_xl);
    cudaGetSymbolAddress((void**)&wqh, g_wqkvT_h);
    cudaGetSymbolAddress((void**)&wql, g_wqkvT_l);
    cudaGetSymbolAddress((void**)&woh, g_woutT_h);
    cudaGetSymbolAddress((void**)&wol, g_woutT_l);
    cudaGetSymbolAddress((void**)&ch, g_ctxh);
    cudaGetSymbolAddress((void**)&cl, g_ctxl);

    const int GEMM_SMEM  = 2 * STAGE_B;   // 81920
    const int FLASH_SMEM = (64*132 + 64*128 + 128*68 + 128*132 + 128*17 + 3*128) * 4;
    cudaFuncSetAttribute(gemm_mma_kernel,
                         cudaFuncAttributeMaxDynamicSharedMemorySize, GEMM_SMEM);
    cudaFuncSetAttribute(flash_attn_kernel,
                         cudaFuncAttributeMaxDynamicSharedMemorySize, FLASH_SMEM);

    // 0) conversions
    convert_split_kernel<<<2048, 256>>>(x, xh, xl, MTOT * DMODEL / 4);
    transpose_split_kernel<<<dim3(N_QKV / 32, DMODEL / 32), dim3(32, 8)>>>(
        w_qkv, wqh, wql, DMODEL, N_QKV);
    transpose_split_kernel<<<dim3(DMODEL / 32, DMODEL / 32), dim3(32, 8)>>>(
        w_out, woh, wol, DMODEL, DMODEL);

    // 1) QKV projection (tensor cores, bf16 split)
    {
        dim3 grid(N_QKV / 128, MTOT / 128);
        gemm_mma_kernel<<<grid, 256, GEMM_SMEM>>>(xh, xl, wqh, wql, b_qkv, qkv_ptr,
                                                  MTOT, N_QKV, DMODEL);
    }
    // 2) Flash attention (fp32), writes ctx hi/lo bf16
    {
        dim3 grid(SEQ / 128, NHEAD, BATCH);
        flash_attn_kernel<<<grid, 256, FLASH_SMEM>>>(qkv_ptr, ch, cl);
    }
    // 3) Output projection (tensor cores, bf16 split)
    {
        dim3 grid(DMODEL / 128, MTOT / 128);
        gemm_mma_kernel<<<grid, 256, GEMM_SMEM>>>(ch, cl, woh, wol, b_out, out,
                                                  MTOT, DMODEL, DMODEL);
    }
}

// round 5
// speedup vs baseline: 4.1940x; 2.0118x over previous
#include <cuda_runtime.h>
#include <cuda_bf16.h>
#include <math.h>
#include <stdint.h>

#define BATCH 2
#define SEQ   2048
#define DMODEL 1024
#define NHEAD 16
#define DHEAD 64
#define MTOT  (BATCH*SEQ)          // 4096
#define N_QKV (3*DMODEL)           // 3072

// ---------------------------------------------------------------------------
// Scratch (__device__ globals)
// ---------------------------------------------------------------------------
#define HTOT (BATCH*NHEAD)         // 32
__device__ __nv_bfloat16 g_xh[(size_t)MTOT * DMODEL];
__device__ __nv_bfloat16 g_xl[(size_t)MTOT * DMODEL];
__device__ __nv_bfloat16 g_wqkvT_h[(size_t)N_QKV * DMODEL];
__device__ __nv_bfloat16 g_wqkvT_l[(size_t)N_QKV * DMODEL];
__device__ __nv_bfloat16 g_woutT_h[(size_t)DMODEL * DMODEL];
__device__ __nv_bfloat16 g_woutT_l[(size_t)DMODEL * DMODEL];
// head-major [b,h,s,d] bf16 hi/lo
__device__ __nv_bfloat16 g_qh[(size_t)HTOT * SEQ * DHEAD];
__device__ __nv_bfloat16 g_ql[(size_t)HTOT * SEQ * DHEAD];
__device__ __nv_bfloat16 g_kh[(size_t)HTOT * SEQ * DHEAD];
__device__ __nv_bfloat16 g_kl[(size_t)HTOT * SEQ * DHEAD];
__device__ __nv_bfloat16 g_vh[(size_t)HTOT * SEQ * DHEAD];
__device__ __nv_bfloat16 g_vl[(size_t)HTOT * SEQ * DHEAD];
// ctx [b,s,(h,d)] hi/lo
__device__ __nv_bfloat16 g_ctxh[(size_t)MTOT * DMODEL];
__device__ __nv_bfloat16 g_ctxl[(size_t)MTOT * DMODEL];

// ---------------------------------------------------------------------------
// Helpers
// ---------------------------------------------------------------------------
__device__ __forceinline__ uint32_t smem_to_u32(const void* p) {
    uint32_t a;
    asm("{ .reg .u64 t; cvta.to.shared.u64 t, %1; cvt.u32.u64 %0, t; }" : "=r"(a) : "l"(p));
    return a;
}
__device__ __forceinline__ void ldsm_x4(uint32_t& r0, uint32_t& r1, uint32_t& r2,
                                        uint32_t& r3, uint32_t addr) {
    asm volatile("ldmatrix.sync.aligned.m8n8.x4.shared.b16 {%0,%1,%2,%3}, [%4];"
                 : "=r"(r0), "=r"(r1), "=r"(r2), "=r"(r3) : "r"(addr));
}
__device__ __forceinline__ void ldsm_x4t(uint32_t& r0, uint32_t& r1, uint32_t& r2,
                                         uint32_t& r3, uint32_t addr) {
    asm volatile("ldmatrix.sync.aligned.m8n8.x4.trans.shared.b16 {%0,%1,%2,%3}, [%4];"
                 : "=r"(r0), "=r"(r1), "=r"(r2), "=r"(r3) : "r"(addr));
}
__device__ __forceinline__ void mma_bf16(float* c, const uint32_t* a, const uint32_t* b) {
    asm volatile(
        "mma.sync.aligned.m16n8k16.row.col.f32.bf16.bf16.f32 "
        "{%0,%1,%2,%3}, {%4,%5,%6,%7}, {%8,%9}, {%0,%1,%2,%3};"
        : "+f"(c[0]), "+f"(c[1]), "+f"(c[2]), "+f"(c[3])
        : "r"(a[0]), "r"(a[1]), "r"(a[2]), "r"(a[3]), "r"(b[0]), "r"(b[1]));
}
__device__ __forceinline__ void cp_async16(uint32_t saddr, const void* gaddr) {
    asm volatile("cp.async.cg.shared.global [%0], [%1], 16;" :: "r"(saddr), "l"(gaddr));
}
#define CP_COMMIT() asm volatile("cp.async.commit_group;" ::: "memory")

// pack two fp32 -> bf16x2 (lo=x, hi=y) and residual lo-part bf16x2
__device__ __forceinline__ void pack_split(float x, float y, uint32_t& hi, uint32_t& lo) {
    uint32_t h;
    asm("cvt.rn.bf16x2.f32 %0, %1, %2;" : "=r"(h) : "f"(y), "f"(x));
    float rx = x - __uint_as_float(h << 16);
    float ry = y - __uint_as_float(h & 0xffff0000u);
    uint32_t l;
    asm("cvt.rn.bf16x2.f32 %0, %1, %2;" : "=r"(l) : "f"(ry), "f"(rx));
    hi = h; lo = l;
}

// ---------------------------------------------------------------------------
// fp32 -> (hi, lo) bf16 split (for x)
// ---------------------------------------------------------------------------
__global__ void convert_split_kernel(const float* __restrict__ in,
                                     __nv_bfloat16* __restrict__ oh,
                                     __nv_bfloat16* __restrict__ ol, int n4)
{
    for (int i = blockIdx.x * blockDim.x + threadIdx.x; i < n4; i += gridDim.x * blockDim.x) {
        float4 v = *(const float4*)(in + (size_t)i * 4);
        uint32_t h0, l0, h1, l1;
        pack_split(v.x, v.y, h0, l0);
        pack_split(v.z, v.w, h1, l1);
        uint32_t* ph = (uint32_t*)(oh + (size_t)i * 4);
        uint32_t* pl = (uint32_t*)(ol + (size_t)i * 4);
        ph[0] = h0; ph[1] = h1;
        pl[0] = l0; pl[1] = l1;
    }
}

// ---------------------------------------------------------------------------
// w[K][N] fp32 -> wT hi/lo [N][K] bf16
// ---------------------------------------------------------------------------
__global__ void transpose_split_kernel(const float* __restrict__ w,
                                       __nv_bfloat16* __restrict__ th,
                                       __nv_bfloat16* __restrict__ tl,
                                       int K, int N)
{
    __shared__ float tile[32][33];
    const int tx = threadIdx.x, ty = threadIdx.y;
    const int x0 = blockIdx.x * 32;
    const int y0 = blockIdx.y * 32;
    #pragma unroll
    for (int i = 0; i < 4; i++) {
        int kl = ty + i * 8;
        tile[kl][tx] = w[(size_t)(y0 + kl) * N + x0 + tx];
    }
    __syncthreads();
    #pragma unroll
    for (int i = 0; i < 4; i++) {
        int nl = ty + i * 8;
        float v = tile[tx][nl];
        __nv_bfloat16 h = __float2bfloat16_rn(v);
        __nv_bfloat16 l = __float2bfloat16_rn(v - __bfloat162float(h));
        th[(size_t)(x0 + nl) * K + y0 + tx] = h;
        tl[(size_t)(x0 + nl) * K + y0 + tx] = l;
    }
}

// ---------------------------------------------------------------------------
// bf16-split tensor GEMM (mma.sync), CTA 128x128 BK32, 8 warps, double buffer.
// QKV_EPI=true : scatter epilogue -> q/k/v head-major bf16 hi/lo (q pre-scaled)
// QKV_EPI=false: fp32 + bias -> C
// ---------------------------------------------------------------------------
#define TILE_B   (128 * 80)
#define STAGE_B  (4 * TILE_B)

template<bool QKV_EPI>
__global__ __launch_bounds__(256)
void gemm_mma_kernel(const __nv_bfloat16* __restrict__ Ah, const __nv_bfloat16* __restrict__ Al,
                     const __nv_bfloat16* __restrict__ Bh, const __nv_bfloat16* __restrict__ Bl,
                     const float* __restrict__ bias, float* __restrict__ C,
                     __nv_bfloat16* __restrict__ qh, __nv_bfloat16* __restrict__ ql,
                     __nv_bfloat16* __restrict__ kh, __nv_bfloat16* __restrict__ kl,
                     __nv_bfloat16* __restrict__ vh, __nv_bfloat16* __restrict__ vl,
                     int M, int N, int K)
{
    extern __shared__ __align__(16) char smem[];
    const uint32_t sbase = smem_to_u32(smem);

    const int tid = threadIdx.x;
    const int lane = tid & 31;
    const int wid = tid >> 5;
    const int warp_m = wid >> 2;
    const int warp_n = wid & 3;
    const int bM = blockIdx.y * 128, bN = blockIdx.x * 128;

    const int grow = tid >> 2;
    const int gslot = tid & 3;
    const int NT = K / 32;

    auto issue = [&](int t) {
        const uint32_t sb = sbase + (t & 1) * STAGE_B;
        const int kof = t * 32 + gslot * 8;
        #pragma unroll
        for (int p = 0; p < 2; p++) {
            const int r = grow + p * 64;
            const uint32_t so = (uint32_t)(r * 80 + gslot * 16);
            cp_async16(sb + so,              Ah + (size_t)(bM + r) * K + kof);
            cp_async16(sb + TILE_B + so,     Al + (size_t)(bM + r) * K + kof);
            cp_async16(sb + 2 * TILE_B + so, Bh + (size_t)(bN + r) * K + kof);
            cp_async16(sb + 3 * TILE_B + so, Bl + (size_t)(bN + r) * K + kof);
        }
        CP_COMMIT();
    };

    float acc[4][4][4];
    #pragma unroll
    for (int i = 0; i < 4; i++)
        #pragma unroll
        for (int j = 0; j < 4; j++)
            #pragma unroll
            for (int k = 0; k < 4; k++) acc[i][j][k] = 0.f;

    issue(0);

    const int a_row = (lane & 7) + ((lane >> 3) & 1) * 8;
    const int a_sel = (lane >> 4);
    const int b_row = (lane & 7) + ((lane >> 4) << 3);
    const int b_sel = (lane >> 3) & 1;

    for (int t = 0; t < NT; t++) {
        if (t + 1 < NT) issue(t + 1);
        if (t + 1 < NT) asm volatile("cp.async.wait_group 1;" ::: "memory");
        else            asm volatile("cp.async.wait_group 0;" ::: "memory");
        __syncthreads();

        const uint32_t sb  = sbase + (t & 1) * STAGE_B;
        const uint32_t sAh = sb, sAl = sb + TILE_B, sBh = sb + 2 * TILE_B, sBl = sb + 3 * TILE_B;

        #pragma unroll
        for (int kk = 0; kk < 2; kk++) {
            uint32_t bh[8], bl[8];
            {
                const uint32_t ba = (uint32_t)((warp_n * 32 + b_row) * 80 + kk * 32 + b_sel * 16);
                ldsm_x4(bh[0], bh[1], bh[2], bh[3], sBh + ba);
                ldsm_x4(bh[4], bh[5], bh[6], bh[7], sBh + ba + 16 * 80);
                ldsm_x4(bl[0], bl[1], bl[2], bl[3], sBl + ba);
                ldsm_x4(bl[4], bl[5], bl[6], bl[7], sBl + ba + 16 * 80);
            }
            #pragma unroll
            for (int mt = 0; mt < 4; mt++) {
                const uint32_t aa = (uint32_t)((warp_m * 64 + mt * 16 + a_row) * 80
                                               + kk * 32 + a_sel * 16);
                uint32_t ah[4], al[4];
                ldsm_x4(ah[0], ah[1], ah[2], ah[3], sAh + aa);
                ldsm_x4(al[0], al[1], al[2], al[3], sAl + aa);
                #pragma unroll
                for (int nt = 0; nt < 4; nt++) {
                    mma_bf16(acc[mt][nt], ah, &bh[nt * 2]);
                    mma_bf16(acc[mt][nt], ah, &bl[nt * 2]);
                    mma_bf16(acc[mt][nt], al, &bh[nt * 2]);
                }
            }
        }
        __syncthreads();
    }

    if (QKV_EPI) {
        // cols of this CTA all belong to one tensor (bN multiple of 128, 128 | 1024)
        const int tensor = bN >> 10;
        __nv_bfloat16* dh = (tensor == 0) ? qh : (tensor == 1) ? kh : vh;
        __nv_bfloat16* dl = (tensor == 0) ? ql : (tensor == 1) ? kl : vl;
        const float qscale = (tensor == 0) ? 0.125f : 1.0f;
        const int bb = bM >> 11;                 // batch
        #pragma unroll
        for (int mt = 0; mt < 4; mt++) {
            const int srow = (bM & 2047) + warp_m * 64 + mt * 16 + (lane >> 2);
            #pragma unroll
            for (int nt = 0; nt < 4; nt++) {
                const int cg = bN + warp_n * 32 + nt * 8 + (lane & 3) * 2;
                const int hh = (cg & 1023) >> 6;
                const int d  = cg & 63;
                const size_t base = ((size_t)(bb * NHEAD + hh) * SEQ) * DHEAD + d;
                float v0 = (acc[mt][nt][0] + bias[cg])     * qscale;
                float v1 = (acc[mt][nt][1] + bias[cg + 1]) * qscale;
                float v2 = (acc[mt][nt][2] + bias[cg])     * qscale;
                float v3 = (acc[mt][nt][3] + bias[cg + 1]) * qscale;
                uint32_t h0, l0, h1, l1;
                pack_split(v0, v1, h0, l0);
                pack_split(v2, v3, h1, l1);
                *(uint32_t*)(dh + base + (size_t)srow * DHEAD)       = h0;
                *(uint32_t*)(dl + base + (size_t)srow * DHEAD)       = l0;
                *(uint32_t*)(dh + base + (size_t)(srow + 8) * DHEAD) = h1;
                *(uint32_t*)(dl + base + (size_t)(srow + 8) * DHEAD) = l1;
            }
        }
    } else {
        #pragma unroll
        for (int mt = 0; mt < 4; mt++) {
            const int r0 = bM + warp_m * 64 + mt * 16 + (lane >> 2);
            #pragma unroll
            for (int nt = 0; nt < 4; nt++) {
                const int c = bN + warp_n * 32 + nt * 8 + (lane & 3) * 2;
                const float bx = bias[c], by = bias[c + 1];
                *(float2*)(C + (size_t)r0 * N + c) =
                    make_float2(acc[mt][nt][0] + bx, acc[mt][nt][1] + by);
                *(float2*)(C + (size_t)(r0 + 8) * N + c) =
                    make_float2(acc[mt][nt][2] + bx, acc[mt][nt][3] + by);
            }
        }
    }
}

// ---------------------------------------------------------------------------
// Tensor-core flash attention. CTA = (b, h, 128 q rows), 8 warps x 16 rows.
// Q resident in smem; K/V tiles (128x64 hi/lo) double-buffered via cp.async.
// S in register fragments; warp-local online softmax; P->A frags in-register;
// V via ldmatrix.trans. All operands bf16 hi/lo 3-MMA split.
// smem rows padded to 144B for conflict-free ldmatrix.
// ---------------------------------------------------------------------------
#define FS_TILE 18432            // 128 rows * 144B

__global__ __launch_bounds__(256, 1)
void flash_mma_kernel(const __nv_bfloat16* __restrict__ qh, const __nv_bfloat16* __restrict__ ql,
                      const __nv_bfloat16* __restrict__ kh, const __nv_bfloat16* __restrict__ kl,
                      const __nv_bfloat16* __restrict__ vh, const __nv_bfloat16* __restrict__ vl,
                      __nv_bfloat16* __restrict__ ctxh, __nv_bfloat16* __restrict__ ctxl)
{
    extern __shared__ __align__(16) char smem[];
    const uint32_t sb = smem_to_u32(smem);
    const uint32_t QH = sb, QL = sb + FS_TILE;
    // K stage i: KH = sb+2T + i*2T (KL = +T); V stage i: sb+6T + i*2T (VL = +T)
    const int tid = threadIdx.x;
    const int lane = tid & 31;
    const int wid = tid >> 5;
    const int mrow = wid * 16;

    const int qt = blockIdx.x;
    const int bh = blockIdx.z * NHEAD + blockIdx.y;
    const int q0 = qt * 128;

    const size_t headbase = (size_t)bh * SEQ * DHEAD;

    // g2s: thread -> row r=tid>>1, 4 chunks at (tid&1)*4
    const int gr = tid >> 1;
    const int gc = (tid & 1) * 4;
    const uint32_t gso = (uint32_t)(gr * 144 + gc * 16);

    // Q load (own commit group)
    {
        const __nv_bfloat16* pqh = qh + headbase + (size_t)(q0 + gr) * DHEAD + gc * 8;
        const __nv_bfloat16* pql = ql + headbase + (size_t)(q0 + gr) * DHEAD + gc * 8;
        #pragma unroll
        for (int c = 0; c < 4; c++) {
            cp_async16(QH + gso + c * 16, pqh + c * 8);
            cp_async16(QL + gso + c * 16, pql + c * 8);
        }
        CP_COMMIT();
    }

    auto loadKV = [&](int t) {
        const uint32_t bk = sb + 2 * FS_TILE + (t & 1) * 2 * FS_TILE;
        const uint32_t bv = sb + 6 * FS_TILE + (t & 1) * 2 * FS_TILE;
        const size_t g = headbase + (size_t)(t * 128 + gr) * DHEAD + gc * 8;
        #pragma unroll
        for (int c = 0; c < 4; c++) {
            cp_async16(bk + gso + c * 16,           kh + g + c * 8);
            cp_async16(bk + FS_TILE + gso + c * 16, kl + g + c * 8);
            cp_async16(bv + gso + c * 16,           vh + g + c * 8);
            cp_async16(bv + FS_TILE + gso + c * 16, vl + g + c * 8);
        }
        CP_COMMIT();
    };
    loadKV(0);

    // lane fragment offsets
    const int arow = (lane & 7) + ((lane >> 3) & 1) * 8;
    const int asel = (lane >> 4);
    const int brow = (lane & 7) + ((lane >> 4) << 3);
    const int bsel = (lane >> 3) & 1;
    const uint32_t a_off = (uint32_t)((mrow + arow) * 144 + asel * 16);  // + ks*32
    const uint32_t b_off = (uint32_t)(brow * 144 + bsel * 16);           // + np*2304 + ks*32
    const uint32_t v_off = (uint32_t)(arow * 144 + asel * 16);           // + ks*2304 + nt*32

    float m0 = -INFINITY, m1 = -INFINITY, l0 = 0.f, l1 = 0.f;
    float oacc[8][4];
    #pragma unroll
    for (int i = 0; i < 8; i++)
        #pragma unroll
        for (int j = 0; j < 4; j++) oacc[i][j] = 0.f;

    const int NTK = SEQ / 128;
    for (int t = 0; t < NTK; t++) {
        if (t + 1 < NTK) loadKV(t + 1);
        if (t + 1 < NTK) asm volatile("cp.async.wait_group 1;" ::: "memory");
        else             asm volatile("cp.async.wait_group 0;" ::: "memory");
        __syncthreads();

        const uint32_t KHB = sb + 2 * FS_TILE + (t & 1) * 2 * FS_TILE;
        const uint32_t KLB = KHB + FS_TILE;
        const uint32_t VHB = sb + 6 * FS_TILE + (t & 1) * 2 * FS_TILE;
        const uint32_t VLB = VHB + FS_TILE;

        // ---- S = Q K^T ----
        float sacc[16][4];
        #pragma unroll
        for (int i = 0; i < 16; i++)
            #pragma unroll
            for (int j = 0; j < 4; j++) sacc[i][j] = 0.f;

        #pragma unroll
        for (int ks = 0; ks < 4; ks++) {
            uint32_t aqh[4], aql[4];
            ldsm_x4(aqh[0], aqh[1], aqh[2], aqh[3], QH + a_off + ks * 32);
            ldsm_x4(aql[0], aql[1], aql[2], aql[3], QL + a_off + ks * 32);
            #pragma unroll
            for (int np = 0; np < 8; np++) {
                uint32_t kbh[4], kbl[4];
                const uint32_t ko = b_off + (uint32_t)(np * 2304 + ks * 32);
                ldsm_x4(kbh[0], kbh[1], kbh[2], kbh[3], KHB + ko);
                ldsm_x4(kbl[0], kbl[1], kbl[2], kbl[3], KLB + ko);
                mma_bf16(sacc[np * 2],     aqh, &kbh[0]);
                mma_bf16(sacc[np * 2],     aqh, &kbl[0]);
                mma_bf16(sacc[np * 2],     aql, &kbh[0]);
                mma_bf16(sacc[np * 2 + 1], aqh, &kbh[2]);
                mma_bf16(sacc[np * 2 + 1], aqh, &kbl[2]);
                mma_bf16(sacc[np * 2 + 1], aql, &kbh[2]);
            }
        }

        // ---- online softmax (warp-local; rows r=lane>>2 and r+8) ----
        float mx0 = -INFINITY, mx1 = -INFINITY;
        #pragma unroll
        for (int i = 0; i < 16; i++) {
            mx0 = fmaxf(mx0, fmaxf(sacc[i][0], sacc[i][1]));
            mx1 = fmaxf(mx1, fmaxf(sacc[i][2], sacc[i][3]));
        }
        mx0 = fmaxf(mx0, __shfl_xor_sync(0xffffffffu, mx0, 1));
        mx0 = fmaxf(mx0, __shfl_xor_sync(0xffffffffu, mx0, 2));
        mx1 = fmaxf(mx1, __shfl_xor_sync(0xffffffffu, mx1, 1));
        mx1 = fmaxf(mx1, __shfl_xor_sync(0xffffffffu, mx1, 2));
        const float mn0 = fmaxf(m0, mx0), mn1 = fmaxf(m1, mx1);
        const float c0 = __expf(m0 - mn0), c1 = __expf(m1 - mn1);
        m0 = mn0; m1 = mn1;

        float ps0 = 0.f, ps1 = 0.f;
        #pragma unroll
        for (int i = 0; i < 16; i++) {
            sacc[i][0] = __expf(sacc[i][0] - mn0); ps0 += sacc[i][0];
            sacc[i][1] = __expf(sacc[i][1] - mn0); ps0 += sacc[i][1];
            sacc[i][2] = __expf(sacc[i][2] - mn1); ps1 += sacc[i][2];
            sacc[i][3] = __expf(sacc[i][3] - mn1); ps1 += sacc[i][3];
        }
        ps0 += __shfl_xor_sync(0xffffffffu, ps0, 1);
        ps0 += __shfl_xor_sync(0xffffffffu, ps0, 2);
        ps1 += __shfl_xor_sync(0xffffffffu, ps1, 1);
        ps1 += __shfl_xor_sync(0xffffffffu, ps1, 2);
        l0 = l0 * c0 + ps0;
        l1 = l1 * c1 + ps1;

        #pragma unroll
        for (int i = 0; i < 8; i++) {
            oacc[i][0] *= c0; oacc[i][1] *= c0;
            oacc[i][2] *= c1; oacc[i][3] *= c1;
        }

        // ---- O += P V ----
        #pragma unroll
        for (int ks = 0; ks < 8; ks++) {
            uint32_t ah[4], al[4];
            pack_split(sacc[2 * ks][0],     sacc[2 * ks][1],     ah[0], al[0]);
            pack_split(sacc[2 * ks][2],     sacc[2 * ks][3],     ah[1], al[1]);
            pack_split(sacc[2 * ks + 1][0], sacc[2 * ks + 1][1], ah[2], al[2]);
            pack_split(sacc[2 * ks + 1][2], sacc[2 * ks + 1][3], ah[3], al[3]);
            #pragma unroll
            for (int nt = 0; nt < 4; nt++) {
                uint32_t vbh[4], vbl[4];
                const uint32_t vo = v_off + (uint32_t)(ks * 2304 + nt * 32);
                ldsm_x4t(vbh[0], vbh[1], vbh[2], vbh[3], VHB + vo);
                ldsm_x4t(vbl[0], vbl[1], vbl[2], vbl[3], VLB + vo);
                mma_bf16(oacc[nt * 2],     ah, &vbh[0]);
                mma_bf16(oacc[nt * 2],     ah, &vbl[0]);
                mma_bf16(oacc[nt * 2],     al, &vbh[0]);
                mma_bf16(oacc[nt * 2 + 1], ah, &vbh[2]);
                mma_bf16(oacc[nt * 2 + 1], ah, &vbl[2]);
                mma_bf16(oacc[nt * 2 + 1], al, &vbh[2]);
            }
        }
        __syncthreads();
    }

    // ---- epilogue: normalize, split, write ctx [b, s, h*64+d] ----
    const float inv0 = 1.f / l0, inv1 = 1.f / l1;
    const int row0 = q0 + mrow + (lane >> 2);
    const size_t base0 = ((size_t)blockIdx.z * SEQ + row0) * DMODEL
                         + blockIdx.y * DHEAD + (lane & 3) * 2;
    const size_t base1 = base0 + 8 * DMODEL;
    #pragma unroll
    for (int nt = 0; nt < 8; nt++) {
        uint32_t h, l;
        pack_split(oacc[nt][0] * inv0, oacc[nt][1] * inv0, h, l);
        *(uint32_t*)(ctxh + base0 + nt * 8) = h;
        *(uint32_t*)(ctxl + base0 + nt * 8) = l;
        pack_split(oacc[nt][2] * inv1, oacc[nt][3] * inv1, h, l);
        *(uint32_t*)(ctxh + base1 + nt * 8) = h;
        *(uint32_t*)(ctxl + base1 + nt * 8) = l;
    }
}

// ---------------------------------------------------------------------------
extern "C" void kernel_launch(void* const* d_in, const int* in_sizes, int n_in,
                              void* d_out, int out_size)
{
    const float* x      = (const float*)d_in[0];
    const float* w_qkv  = (const float*)d_in[1];
    const float* b_qkv  = (const float*)d_in[2];
    const float* w_out  = (const float*)d_in[3];
    const float* b_out  = (const float*)d_in[4];
    float* out = (float*)d_out;

    __nv_bfloat16 *xh, *xl, *wqh, *wql, *woh, *wol;
    __nv_bfloat16 *qh, *ql, *kh, *kl, *vh, *vl, *ch, *cl;
    cudaGetSymbolAddress((void**)&xh, g_xh);
    cudaGetSymbolAddress((void**)&xl, g_xl);
    cudaGetSymbolAddress((void**)&wqh, g_wqkvT_h);
    cudaGetSymbolAddress((void**)&wql, g_wqkvT_l);
    cudaGetSymbolAddress((void**)&woh, g_woutT_h);
    cudaGetSymbolAddress((void**)&wol, g_woutT_l);
    cudaGetSymbolAddress((void**)&qh, g_qh);
    cudaGetSymbolAddress((void**)&ql, g_ql);
    cudaGetSymbolAddress((void**)&kh, g_kh);
    cudaGetSymbolAddress((void**)&kl, g_kl);
    cudaGetSymbolAddress((void**)&vh, g_vh);
    cudaGetSymbolAddress((void**)&vl, g_vl);
    cudaGetSymbolAddress((void**)&ch, g_ctxh);
    cudaGetSymbolAddress((void**)&cl, g_ctxl);

    const int GEMM_SMEM  = 2 * STAGE_B;     // 81920
    const int FLASH_SMEM = 10 * FS_TILE;    // 184320
    cudaFuncSetAttribute(gemm_mma_kernel<true>,
                         cudaFuncAttributeMaxDynamicSharedMemorySize, GEMM_SMEM);
    cudaFuncSetAttribute(gemm_mma_kernel<false>,
                         cudaFuncAttributeMaxDynamicSharedMemorySize, GEMM_SMEM);
    cudaFuncSetAttribute(flash_mma_kernel,
                         cudaFuncAttributeMaxDynamicSharedMemorySize, FLASH_SMEM);

    // 0) conversions
    convert_split_kernel<<<2048, 256>>>(x, xh, xl, MTOT * DMODEL / 4);
    transpose_split_kernel<<<dim3(N_QKV / 32, DMODEL / 32), dim3(32, 8)>>>(
        w_qkv, wqh, wql, DMODEL, N_QKV);
    transpose_split_kernel<<<dim3(DMODEL / 32, DMODEL / 32), dim3(32, 8)>>>(
        w_out, woh, wol, DMODEL, DMODEL);

    // 1) QKV projection -> q/k/v head-major bf16 hi/lo (q pre-scaled)
    {
        dim3 grid(N_QKV / 128, MTOT / 128);
        gemm_mma_kernel<true><<<grid, 256, GEMM_SMEM>>>(
            xh, xl, wqh, wql, b_qkv, nullptr,
            qh, ql, kh, kl, vh, vl, MTOT, N_QKV, DMODEL);
    }
    // 2) Tensor-core flash attention -> ctx hi/lo
    {
        dim3 grid(SEQ / 128, NHEAD, BATCH);
        flash_mma_kernel<<<grid, 256, FLASH_SMEM>>>(qh, ql, kh, kl, vh, vl, ch, cl);
    }
    // 3) Output projection -> fp32 out
    {
        dim3 grid(DMODEL / 128, MTOT / 128);
        gemm_mma_kernel<false><<<grid, 256, GEMM_SMEM>>>(
            ch, cl, woh, wol, b_out, out,
            nullptr, nullptr, nullptr, nullptr, nullptr, nullptr,
            MTOT, DMODEL, DMODEL);
    }
}

// round 6
// speedup vs baseline: 4.2430x; 1.0117x over previous
#include <cuda_runtime.h>
#include <cuda_bf16.h>
#include <math.h>
#include <stdint.h>

#define BATCH 2
#define SEQ   2048
#define DMODEL 1024
#define NHEAD 16
#define DHEAD 64
#define MTOT  (BATCH*SEQ)          // 4096
#define N_QKV (3*DMODEL)           // 3072

// ---------------------------------------------------------------------------
// Scratch (__device__ globals)
// ---------------------------------------------------------------------------
#define HTOT (BATCH*NHEAD)         // 32
__device__ __nv_bfloat16 g_xh[(size_t)MTOT * DMODEL];
__device__ __nv_bfloat16 g_xl[(size_t)MTOT * DMODEL];
__device__ __nv_bfloat16 g_wqkvT_h[(size_t)N_QKV * DMODEL];
__device__ __nv_bfloat16 g_wqkvT_l[(size_t)N_QKV * DMODEL];
__device__ __nv_bfloat16 g_woutT_h[(size_t)DMODEL * DMODEL];
__device__ __nv_bfloat16 g_woutT_l[(size_t)DMODEL * DMODEL];
// head-major [b,h,s,d] bf16 hi/lo
__device__ __nv_bfloat16 g_qh[(size_t)HTOT * SEQ * DHEAD];
__device__ __nv_bfloat16 g_ql[(size_t)HTOT * SEQ * DHEAD];
__device__ __nv_bfloat16 g_kh[(size_t)HTOT * SEQ * DHEAD];
__device__ __nv_bfloat16 g_kl[(size_t)HTOT * SEQ * DHEAD];
__device__ __nv_bfloat16 g_vh[(size_t)HTOT * SEQ * DHEAD];
__device__ __nv_bfloat16 g_vl[(size_t)HTOT * SEQ * DHEAD];
// ctx [b,s,(h,d)] hi/lo
__device__ __nv_bfloat16 g_ctxh[(size_t)MTOT * DMODEL];
__device__ __nv_bfloat16 g_ctxl[(size_t)MTOT * DMODEL];

// ---------------------------------------------------------------------------
// Helpers
// ---------------------------------------------------------------------------
__device__ __forceinline__ uint32_t smem_to_u32(const void* p) {
    uint32_t a;
    asm("{ .reg .u64 t; cvta.to.shared.u64 t, %1; cvt.u32.u64 %0, t; }" : "=r"(a) : "l"(p));
    return a;
}
__device__ __forceinline__ void ldsm_x4(uint32_t& r0, uint32_t& r1, uint32_t& r2,
                                        uint32_t& r3, uint32_t addr) {
    asm volatile("ldmatrix.sync.aligned.m8n8.x4.shared.b16 {%0,%1,%2,%3}, [%4];"
                 : "=r"(r0), "=r"(r1), "=r"(r2), "=r"(r3) : "r"(addr));
}
__device__ __forceinline__ void ldsm_x4t(uint32_t& r0, uint32_t& r1, uint32_t& r2,
                                         uint32_t& r3, uint32_t addr) {
    asm volatile("ldmatrix.sync.aligned.m8n8.x4.trans.shared.b16 {%0,%1,%2,%3}, [%4];"
                 : "=r"(r0), "=r"(r1), "=r"(r2), "=r"(r3) : "r"(addr));
}
__device__ __forceinline__ void mma_bf16(float* c, const uint32_t* a, const uint32_t* b) {
    asm volatile(
        "mma.sync.aligned.m16n8k16.row.col.f32.bf16.bf16.f32 "
        "{%0,%1,%2,%3}, {%4,%5,%6,%7}, {%8,%9}, {%0,%1,%2,%3};"
        : "+f"(c[0]), "+f"(c[1]), "+f"(c[2]), "+f"(c[3])
        : "r"(a[0]), "r"(a[1]), "r"(a[2]), "r"(a[3]), "r"(b[0]), "r"(b[1]));
}
__device__ __forceinline__ void cp_async16(uint32_t saddr, const void* gaddr) {
    asm volatile("cp.async.cg.shared.global [%0], [%1], 16;" :: "r"(saddr), "l"(gaddr));
}
#define CP_COMMIT() asm volatile("cp.async.commit_group;" ::: "memory")
#define CP_WAIT0()  asm volatile("cp.async.wait_group 0;" ::: "memory")

// pack two fp32 -> bf16x2 hi + residual bf16x2 lo
__device__ __forceinline__ void pack_split(float x, float y, uint32_t& hi, uint32_t& lo) {
    uint32_t h;
    asm("cvt.rn.bf16x2.f32 %0, %1, %2;" : "=r"(h) : "f"(y), "f"(x));
    float rx = x - __uint_as_float(h << 16);
    float ry = y - __uint_as_float(h & 0xffff0000u);
    uint32_t l;
    asm("cvt.rn.bf16x2.f32 %0, %1, %2;" : "=r"(l) : "f"(ry), "f"(rx));
    hi = h; lo = l;
}

// ---------------------------------------------------------------------------
// fp32 -> (hi, lo) bf16 split (for x)
// ---------------------------------------------------------------------------
__global__ void convert_split_kernel(const float* __restrict__ in,
                                     __nv_bfloat16* __restrict__ oh,
                                     __nv_bfloat16* __restrict__ ol, int n4)
{
    for (int i = blockIdx.x * blockDim.x + threadIdx.x; i < n4; i += gridDim.x * blockDim.x) {
        float4 v = *(const float4*)(in + (size_t)i * 4);
        uint32_t h0, l0, h1, l1;
        pack_split(v.x, v.y, h0, l0);
        pack_split(v.z, v.w, h1, l1);
        uint32_t* ph = (uint32_t*)(oh + (size_t)i * 4);
        uint32_t* pl = (uint32_t*)(ol + (size_t)i * 4);
        ph[0] = h0; ph[1] = h1;
        pl[0] = l0; pl[1] = l1;
    }
}

// ---------------------------------------------------------------------------
// w[K][N] fp32 -> wT hi/lo [N][K] bf16
// ---------------------------------------------------------------------------
__global__ void transpose_split_kernel(const float* __restrict__ w,
                                       __nv_bfloat16* __restrict__ th,
                                       __nv_bfloat16* __restrict__ tl,
                                       int K, int N)
{
    __shared__ float tile[32][33];
    const int tx = threadIdx.x, ty = threadIdx.y;
    const int x0 = blockIdx.x * 32;
    const int y0 = blockIdx.y * 32;
    #pragma unroll
    for (int i = 0; i < 4; i++) {
        int kl = ty + i * 8;
        tile[kl][tx] = w[(size_t)(y0 + kl) * N + x0 + tx];
    }
    __syncthreads();
    #pragma unroll
    for (int i = 0; i < 4; i++) {
        int nl = ty + i * 8;
        float v = tile[tx][nl];
        __nv_bfloat16 h = __float2bfloat16_rn(v);
        __nv_bfloat16 l = __float2bfloat16_rn(v - __bfloat162float(h));
        th[(size_t)(x0 + nl) * K + y0 + tx] = h;
        tl[(size_t)(x0 + nl) * K + y0 + tx] = l;
    }
}

// ---------------------------------------------------------------------------
// bf16-split tensor GEMM (mma.sync), CTA 128x128 BK32, 8 warps.
// Single-sync pipelined mainloop: wait0 -> sync -> issue(t+1) -> compute.
// ---------------------------------------------------------------------------
#define TILE_B   (128 * 80)
#define STAGE_B  (4 * TILE_B)

template<bool QKV_EPI>
__global__ __launch_bounds__(256)
void gemm_mma_kernel(const __nv_bfloat16* __restrict__ Ah, const __nv_bfloat16* __restrict__ Al,
                     const __nv_bfloat16* __restrict__ Bh, const __nv_bfloat16* __restrict__ Bl,
                     const float* __restrict__ bias, float* __restrict__ C,
                     __nv_bfloat16* __restrict__ qh, __nv_bfloat16* __restrict__ ql,
                     __nv_bfloat16* __restrict__ kh, __nv_bfloat16* __restrict__ kl,
                     __nv_bfloat16* __restrict__ vh, __nv_bfloat16* __restrict__ vl,
                     int M, int N, int K)
{
    extern __shared__ __align__(16) char smem[];
    const uint32_t sbase = smem_to_u32(smem);

    const int tid = threadIdx.x;
    const int lane = tid & 31;
    const int wid = tid >> 5;
    const int warp_m = wid >> 2;
    const int warp_n = wid & 3;
    const int bM = blockIdx.y * 128, bN = blockIdx.x * 128;

    const int grow = tid >> 2;
    const int gslot = tid & 3;
    const int NT = K / 32;

    auto issue = [&](int t) {
        const uint32_t sb = sbase + (t & 1) * STAGE_B;
        const int kof = t * 32 + gslot * 8;
        #pragma unroll
        for (int p = 0; p < 2; p++) {
            const int r = grow + p * 64;
            const uint32_t so = (uint32_t)(r * 80 + gslot * 16);
            cp_async16(sb + so,              Ah + (size_t)(bM + r) * K + kof);
            cp_async16(sb + TILE_B + so,     Al + (size_t)(bM + r) * K + kof);
            cp_async16(sb + 2 * TILE_B + so, Bh + (size_t)(bN + r) * K + kof);
            cp_async16(sb + 3 * TILE_B + so, Bl + (size_t)(bN + r) * K + kof);
        }
        CP_COMMIT();
    };

    float acc[4][4][4];
    #pragma unroll
    for (int i = 0; i < 4; i++)
        #pragma unroll
        for (int j = 0; j < 4; j++)
            #pragma unroll
            for (int k = 0; k < 4; k++) acc[i][j][k] = 0.f;

    issue(0);

    const int a_row = (lane & 7) + ((lane >> 3) & 1) * 8;
    const int a_sel = (lane >> 4);
    const int b_row = (lane & 7) + ((lane >> 4) << 3);
    const int b_sel = (lane >> 3) & 1;

    for (int t = 0; t < NT; t++) {
        CP_WAIT0();
        __syncthreads();
        if (t + 1 < NT) issue(t + 1);   // overlaps compute below; buffer safe past sync

        const uint32_t sb  = sbase + (t & 1) * STAGE_B;
        const uint32_t sAh = sb, sAl = sb + TILE_B, sBh = sb + 2 * TILE_B, sBl = sb + 3 * TILE_B;

        #pragma unroll
        for (int kk = 0; kk < 2; kk++) {
            uint32_t bh[8], bl[8];
            {
                const uint32_t ba = (uint32_t)((warp_n * 32 + b_row) * 80 + kk * 32 + b_sel * 16);
                ldsm_x4(bh[0], bh[1], bh[2], bh[3], sBh + ba);
                ldsm_x4(bh[4], bh[5], bh[6], bh[7], sBh + ba + 16 * 80);
                ldsm_x4(bl[0], bl[1], bl[2], bl[3], sBl + ba);
                ldsm_x4(bl[4], bl[5], bl[6], bl[7], sBl + ba + 16 * 80);
            }
            #pragma unroll
            for (int mt = 0; mt < 4; mt++) {
                const uint32_t aa = (uint32_t)((warp_m * 64 + mt * 16 + a_row) * 80
                                               + kk * 32 + a_sel * 16);
                uint32_t ah[4], al[4];
                ldsm_x4(ah[0], ah[1], ah[2], ah[3], sAh + aa);
                ldsm_x4(al[0], al[1], al[2], al[3], sAl + aa);
                #pragma unroll
                for (int nt = 0; nt < 4; nt++) {
                    mma_bf16(acc[mt][nt], ah, &bh[nt * 2]);
                    mma_bf16(acc[mt][nt], ah, &bl[nt * 2]);
                    mma_bf16(acc[mt][nt], al, &bh[nt * 2]);
                }
            }
        }
    }

    if (QKV_EPI) {
        const int tensor = bN >> 10;
        __nv_bfloat16* dh = (tensor == 0) ? qh : (tensor == 1) ? kh : vh;
        __nv_bfloat16* dl = (tensor == 0) ? ql : (tensor == 1) ? kl : vl;
        const float qscale = (tensor == 0) ? 0.125f : 1.0f;
        const int bb = bM >> 11;
        #pragma unroll
        for (int mt = 0; mt < 4; mt++) {
            const int srow = (bM & 2047) + warp_m * 64 + mt * 16 + (lane >> 2);
            #pragma unroll
            for (int nt = 0; nt < 4; nt++) {
                const int cg = bN + warp_n * 32 + nt * 8 + (lane & 3) * 2;
                const int hh = (cg & 1023) >> 6;
                const int d  = cg & 63;
                const size_t base = ((size_t)(bb * NHEAD + hh) * SEQ) * DHEAD + d;
                float v0 = (acc[mt][nt][0] + bias[cg])     * qscale;
                float v1 = (acc[mt][nt][1] + bias[cg + 1]) * qscale;
                float v2 = (acc[mt][nt][2] + bias[cg])     * qscale;
                float v3 = (acc[mt][nt][3] + bias[cg + 1]) * qscale;
                uint32_t h0, l0, h1, l1;
                pack_split(v0, v1, h0, l0);
                pack_split(v2, v3, h1, l1);
                *(uint32_t*)(dh + base + (size_t)srow * DHEAD)       = h0;
                *(uint32_t*)(dl + base + (size_t)srow * DHEAD)       = l0;
                *(uint32_t*)(dh + base + (size_t)(srow + 8) * DHEAD) = h1;
                *(uint32_t*)(dl + base + (size_t)(srow + 8) * DHEAD) = l1;
            }
        }
    } else {
        #pragma unroll
        for (int mt = 0; mt < 4; mt++) {
            const int r0 = bM + warp_m * 64 + mt * 16 + (lane >> 2);
            #pragma unroll
            for (int nt = 0; nt < 4; nt++) {
                const int c = bN + warp_n * 32 + nt * 8 + (lane & 3) * 2;
                const float bx = bias[c], by = bias[c + 1];
                *(float2*)(C + (size_t)r0 * N + c) =
                    make_float2(acc[mt][nt][0] + bx, acc[mt][nt][1] + by);
                *(float2*)(C + (size_t)(r0 + 8) * N + c) =
                    make_float2(acc[mt][nt][2] + bx, acc[mt][nt][3] + by);
            }
        }
    }
}

// ---------------------------------------------------------------------------
// Tensor-core flash attention, single-sync pipelined KV loop, Q frags hoisted.
// ---------------------------------------------------------------------------
#define FS_TILE 18432            // 128 rows * 144B

__global__ __launch_bounds__(256, 1)
void flash_mma_kernel(const __nv_bfloat16* __restrict__ qh, const __nv_bfloat16* __restrict__ ql,
                      const __nv_bfloat16* __restrict__ kh, const __nv_bfloat16* __restrict__ kl,
                      const __nv_bfloat16* __restrict__ vh, const __nv_bfloat16* __restrict__ vl,
                      __nv_bfloat16* __restrict__ ctxh, __nv_bfloat16* __restrict__ ctxl)
{
    extern __shared__ __align__(16) char smem[];
    const uint32_t sb = smem_to_u32(smem);
    const uint32_t QH = sb, QL = sb + FS_TILE;
    const int tid = threadIdx.x;
    const int lane = tid & 31;
    const int wid = tid >> 5;
    const int mrow = wid * 16;

    const int qt = blockIdx.x;
    const int bh = blockIdx.z * NHEAD + blockIdx.y;
    const int q0 = qt * 128;

    const size_t headbase = (size_t)bh * SEQ * DHEAD;

    const int gr = tid >> 1;
    const int gc = (tid & 1) * 4;
    const uint32_t gso = (uint32_t)(gr * 144 + gc * 16);

    // Q load
    {
        const __nv_bfloat16* pqh = qh + headbase + (size_t)(q0 + gr) * DHEAD + gc * 8;
        const __nv_bfloat16* pql = ql + headbase + (size_t)(q0 + gr) * DHEAD + gc * 8;
        #pragma unroll
        for (int c = 0; c < 4; c++) {
            cp_async16(QH + gso + c * 16, pqh + c * 8);
            cp_async16(QL + gso + c * 16, pql + c * 8);
        }
        CP_COMMIT();
    }

    auto loadKV = [&](int t) {
        const uint32_t bk = sb + 2 * FS_TILE + (t & 1) * 2 * FS_TILE;
        const uint32_t bv = sb + 6 * FS_TILE + (t & 1) * 2 * FS_TILE;
        const size_t g = headbase + (size_t)(t * 128 + gr) * DHEAD + gc * 8;
        #pragma unroll
        for (int c = 0; c < 4; c++) {
            cp_async16(bk + gso + c * 16,           kh + g + c * 8);
            cp_async16(bk + FS_TILE + gso + c * 16, kl + g + c * 8);
            cp_async16(bv + gso + c * 16,           vh + g + c * 8);
            cp_async16(bv + FS_TILE + gso + c * 16, vl + g + c * 8);
        }
        CP_COMMIT();
    };
    loadKV(0);

    const int arow = (lane & 7) + ((lane >> 3) & 1) * 8;
    const int asel = (lane >> 4);
    const int brow = (lane & 7) + ((lane >> 4) << 3);
    const int bsel = (lane >> 3) & 1;
    const uint32_t a_off = (uint32_t)((mrow + arow) * 144 + asel * 16);
    const uint32_t b_off = (uint32_t)(brow * 144 + bsel * 16);
    const uint32_t v_off = (uint32_t)(arow * 144 + asel * 16);

    uint32_t qfh[4][4], qfl[4][4];   // Q fragments, tile-invariant

    float m0 = -INFINITY, m1 = -INFINITY, l0 = 0.f, l1 = 0.f;
    float oacc[8][4];
    #pragma unroll
    for (int i = 0; i < 8; i++)
        #pragma unroll
        for (int j = 0; j < 4; j++) oacc[i][j] = 0.f;

    const int NTK = SEQ / 128;
    for (int t = 0; t < NTK; t++) {
        CP_WAIT0();
        __syncthreads();
        if (t + 1 < NTK) loadKV(t + 1);   // overlaps compute; buffer safe past sync

        if (t == 0) {
            #pragma unroll
            for (int ks = 0; ks < 4; ks++) {
                ldsm_x4(qfh[ks][0], qfh[ks][1], qfh[ks][2], qfh[ks][3], QH + a_off + ks * 32);
                ldsm_x4(qfl[ks][0], qfl[ks][1], qfl[ks][2], qfl[ks][3], QL + a_off + ks * 32);
            }
        }

        const uint32_t KHB = sb + 2 * FS_TILE + (t & 1) * 2 * FS_TILE;
        const uint32_t KLB = KHB + FS_TILE;
        const uint32_t VHB = sb + 6 * FS_TILE + (t & 1) * 2 * FS_TILE;
        const uint32_t VLB = VHB + FS_TILE;

        // ---- S = Q K^T ----
        float sacc[16][4];
        #pragma unroll
        for (int i = 0; i < 16; i++)
            #pragma unroll
            for (int j = 0; j < 4; j++) sacc[i][j] = 0.f;

        #pragma unroll
        for (int ks = 0; ks < 4; ks++) {
            #pragma unroll
            for (int np = 0; np < 8; np++) {
                uint32_t kbh[4], kbl[4];
                const uint32_t ko = b_off + (uint32_t)(np * 2304 + ks * 32);
                ldsm_x4(kbh[0], kbh[1], kbh[2], kbh[3], KHB + ko);
                ldsm_x4(kbl[0], kbl[1], kbl[2], kbl[3], KLB + ko);
                mma_bf16(sacc[np * 2],     qfh[ks], &kbh[0]);
                mma_bf16(sacc[np * 2],     qfh[ks], &kbl[0]);
                mma_bf16(sacc[np * 2],     qfl[ks], &kbh[0]);
                mma_bf16(sacc[np * 2 + 1], qfh[ks], &kbh[2]);
                mma_bf16(sacc[np * 2 + 1], qfh[ks], &kbl[2]);
                mma_bf16(sacc[np * 2 + 1], qfl[ks], &kbh[2]);
            }
        }

        // ---- online softmax ----
        float mx0 = -INFINITY, mx1 = -INFINITY;
        #pragma unroll
        for (int i = 0; i < 16; i++) {
            mx0 = fmaxf(mx0, fmaxf(sacc[i][0], sacc[i][1]));
            mx1 = fmaxf(mx1, fmaxf(sacc[i][2], sacc[i][3]));
        }
        mx0 = fmaxf(mx0, __shfl_xor_sync(0xffffffffu, mx0, 1));
        mx0 = fmaxf(mx0, __shfl_xor_sync(0xffffffffu, mx0, 2));
        mx1 = fmaxf(mx1, __shfl_xor_sync(0xffffffffu, mx1, 1));
        mx1 = fmaxf(mx1, __shfl_xor_sync(0xffffffffu, mx1, 2));
        const float mn0 = fmaxf(m0, mx0), mn1 = fmaxf(m1, mx1);
        const float c0 = __expf(m0 - mn0), c1 = __expf(m1 - mn1);
        m0 = mn0; m1 = mn1;

        float ps0 = 0.f, ps1 = 0.f;
        #pragma unroll
        for (int i = 0; i < 16; i++) {
            sacc[i][0] = __expf(sacc[i][0] - mn0); ps0 += sacc[i][0];
            sacc[i][1] = __expf(sacc[i][1] - mn0); ps0 += sacc[i][1];
            sacc[i][2] = __expf(sacc[i][2] - mn1); ps1 += sacc[i][2];
            sacc[i][3] = __expf(sacc[i][3] - mn1); ps1 += sacc[i][3];
        }
        ps0 += __shfl_xor_sync(0xffffffffu, ps0, 1);
        ps0 += __shfl_xor_sync(0xffffffffu, ps0, 2);
        ps1 += __shfl_xor_sync(0xffffffffu, ps1, 1);
        ps1 += __shfl_xor_sync(0xffffffffu, ps1, 2);
        l0 = l0 * c0 + ps0;
        l1 = l1 * c1 + ps1;

        #pragma unroll
        for (int i = 0; i < 8; i++) {
            oacc[i][0] *= c0; oacc[i][1] *= c0;
            oacc[i][2] *= c1; oacc[i][3] *= c1;
        }

        // ---- O += P V ----
        #pragma unroll
        for (int ks = 0; ks < 8; ks++) {
            uint32_t ah[4], al[4];
            pack_split(sacc[2 * ks][0],     sacc[2 * ks][1],     ah[0], al[0]);
            pack_split(sacc[2 * ks][2],     sacc[2 * ks][3],     ah[1], al[1]);
            pack_split(sacc[2 * ks + 1][0], sacc[2 * ks + 1][1], ah[2], al[2]);
            pack_split(sacc[2 * ks + 1][2], sacc[2 * ks + 1][3], ah[3], al[3]);
            #pragma unroll
            for (int nt = 0; nt < 4; nt++) {
                uint32_t vbh[4], vbl[4];
                const uint32_t vo = v_off + (uint32_t)(ks * 2304 + nt * 32);
                ldsm_x4t(vbh[0], vbh[1], vbh[2], vbh[3], VHB + vo);
                ldsm_x4t(vbl[0], vbl[1], vbl[2], vbl[3], VLB + vo);
                mma_bf16(oacc[nt * 2],     ah, &vbh[0]);
                mma_bf16(oacc[nt * 2],     ah, &vbl[0]);
                mma_bf16(oacc[nt * 2],     al, &vbh[0]);
                mma_bf16(oacc[nt * 2 + 1], ah, &vbh[2]);
                mma_bf16(oacc[nt * 2 + 1], ah, &vbl[2]);
                mma_bf16(oacc[nt * 2 + 1], al, &vbh[2]);
            }
        }
    }

    // ---- epilogue ----
    const float inv0 = 1.f / l0, inv1 = 1.f / l1;
    const int row0 = q0 + mrow + (lane >> 2);
    const size_t base0 = ((size_t)blockIdx.z * SEQ + row0) * DMODEL
                         + blockIdx.y * DHEAD + (lane & 3) * 2;
    const size_t base1 = base0 + 8 * DMODEL;
    #pragma unroll
    for (int nt = 0; nt < 8; nt++) {
        uint32_t h, l;
        pack_split(oacc[nt][0] * inv0, oacc[nt][1] * inv0, h, l);
        *(uint32_t*)(ctxh + base0 + nt * 8) = h;
        *(uint32_t*)(ctxl + base0 + nt * 8) = l;
        pack_split(oacc[nt][2] * inv1, oacc[nt][3] * inv1, h, l);
        *(uint32_t*)(ctxh + base1 + nt * 8) = h;
        *(uint32_t*)(ctxl + base1 + nt * 8) = l;
    }
}

// ---------------------------------------------------------------------------
extern "C" void kernel_launch(void* const* d_in, const int* in_sizes, int n_in,
                              void* d_out, int out_size)
{
    const float* x      = (const float*)d_in[0];
    const float* w_qkv  = (const float*)d_in[1];
    const float* b_qkv  = (const float*)d_in[2];
    const float* w_out  = (const float*)d_in[3];
    const float* b_out  = (const float*)d_in[4];
    float* out = (float*)d_out;

    __nv_bfloat16 *xh, *xl, *wqh, *wql, *woh, *wol;
    __nv_bfloat16 *qh, *ql, *kh, *kl, *vh, *vl, *ch, *cl;
    cudaGetSymbolAddress((void**)&xh, g_xh);
    cudaGetSymbolAddress((void**)&xl, g_xl);
    cudaGetSymbolAddress((void**)&wqh, g_wqkvT_h);
    cudaGetSymbolAddress((void**)&wql, g_wqkvT_l);
    cudaGetSymbolAddress((void**)&woh, g_woutT_h);
    cudaGetSymbolAddress((void**)&wol, g_woutT_l);
    cudaGetSymbolAddress((void**)&qh, g_qh);
    cudaGetSymbolAddress((void**)&ql, g_ql);
    cudaGetSymbolAddress((void**)&kh, g_kh);
    cudaGetSymbolAddress((void**)&kl, g_kl);
    cudaGetSymbolAddress((void**)&vh, g_vh);
    cudaGetSymbolAddress((void**)&vl, g_vl);
    cudaGetSymbolAddress((void**)&ch, g_ctxh);
    cudaGetSymbolAddress((void**)&cl, g_ctxl);

    const int GEMM_SMEM  = 2 * STAGE_B;     // 81920
    const int FLASH_SMEM = 10 * FS_TILE;    // 184320
    cudaFuncSetAttribute(gemm_mma_kernel<true>,
                         cudaFuncAttributeMaxDynamicSharedMemorySize, GEMM_SMEM);
    cudaFuncSetAttribute(gemm_mma_kernel<false>,
                         cudaFuncAttributeMaxDynamicSharedMemorySize, GEMM_SMEM);
    cudaFuncSetAttribute(flash_mma_kernel,
                         cudaFuncAttributeMaxDynamicSharedMemorySize, FLASH_SMEM);

    // 0) conversions
    convert_split_kernel<<<2048, 256>>>(x, xh, xl, MTOT * DMODEL / 4);
    transpose_split_kernel<<<dim3(N_QKV / 32, DMODEL / 32), dim3(32, 8)>>>(
        w_qkv, wqh, wql, DMODEL, N_QKV);
    transpose_split_kernel<<<dim3(DMODEL / 32, DMODEL / 32), dim3(32, 8)>>>(
        w_out, woh, wol, DMODEL, DMODEL);

    // 1) QKV projection -> q/k/v head-major bf16 hi/lo (q pre-scaled)
    {
        dim3 grid(N_QKV / 128, MTOT / 128);
        gemm_mma_kernel<true><<<grid, 256, GEMM_SMEM>>>(
            xh, xl, wqh, wql, b_qkv, nullptr,
            qh, ql, kh, kl, vh, vl, MTOT, N_QKV, DMODEL);
    }
    // 2) Tensor-core flash attention -> ctx hi/lo
    {
        dim3 grid(SEQ / 128, NHEAD, BATCH);
        flash_mma_kernel<<<grid, 256, FLASH_SMEM>>>(qh, ql, kh, kl, vh, vl, ch, cl);
    }
    // 3) Output projection -> fp32 out
    {
        dim3 grid(DMODEL / 128, MTOT / 128);
        gemm_mma_kernel<false><<<grid, 256, GEMM_SMEM>>>(
            ch, cl, woh, wol, b_out, out,
            nullptr, nullptr, nullptr, nullptr, nullptr, nullptr,
            MTOT, DMODEL, DMODEL);
    }
}

// round 7
// speedup vs baseline: 4.2434x; 1.0001x over previous
#include <cuda_runtime.h>
#include <cuda_bf16.h>
#include <math.h>
#include <stdint.h>

#define BATCH 2
#define SEQ   2048
#define DMODEL 1024
#define NHEAD 16
#define DHEAD 64
#define MTOT  (BATCH*SEQ)          // 4096
#define N_QKV (3*DMODEL)           // 3072

// ---------------------------------------------------------------------------
// Scratch (__device__ globals)
// ---------------------------------------------------------------------------
#define HTOT (BATCH*NHEAD)         // 32
__device__ __nv_bfloat16 g_xh[(size_t)MTOT * DMODEL];
__device__ __nv_bfloat16 g_xl[(size_t)MTOT * DMODEL];
__device__ __nv_bfloat16 g_wqkvT_h[(size_t)N_QKV * DMODEL];
__device__ __nv_bfloat16 g_wqkvT_l[(size_t)N_QKV * DMODEL];
__device__ __nv_bfloat16 g_woutT_h[(size_t)DMODEL * DMODEL];
__device__ __nv_bfloat16 g_woutT_l[(size_t)DMODEL * DMODEL];
// head-major [b,h,s,d] bf16 hi/lo
__device__ __nv_bfloat16 g_qh[(size_t)HTOT * SEQ * DHEAD];
__device__ __nv_bfloat16 g_ql[(size_t)HTOT * SEQ * DHEAD];
__device__ __nv_bfloat16 g_kh[(size_t)HTOT * SEQ * DHEAD];
__device__ __nv_bfloat16 g_kl[(size_t)HTOT * SEQ * DHEAD];
__device__ __nv_bfloat16 g_vh[(size_t)HTOT * SEQ * DHEAD];
__device__ __nv_bfloat16 g_vl[(size_t)HTOT * SEQ * DHEAD];
// ctx [b,s,(h,d)] hi/lo
__device__ __nv_bfloat16 g_ctxh[(size_t)MTOT * DMODEL];
__device__ __nv_bfloat16 g_ctxl[(size_t)MTOT * DMODEL];

// ---------------------------------------------------------------------------
// Helpers
// ---------------------------------------------------------------------------
__device__ __forceinline__ uint32_t smem_to_u32(const void* p) {
    uint32_t a;
    asm("{ .reg .u64 t; cvta.to.shared.u64 t, %1; cvt.u32.u64 %0, t; }" : "=r"(a) : "l"(p));
    return a;
}
__device__ __forceinline__ void ldsm_x4(uint32_t& r0, uint32_t& r1, uint32_t& r2,
                                        uint32_t& r3, uint32_t addr) {
    asm volatile("ldmatrix.sync.aligned.m8n8.x4.shared.b16 {%0,%1,%2,%3}, [%4];"
                 : "=r"(r0), "=r"(r1), "=r"(r2), "=r"(r3) : "r"(addr));
}
__device__ __forceinline__ void ldsm_x4t(uint32_t& r0, uint32_t& r1, uint32_t& r2,
                                         uint32_t& r3, uint32_t addr) {
    asm volatile("ldmatrix.sync.aligned.m8n8.x4.trans.shared.b16 {%0,%1,%2,%3}, [%4];"
                 : "=r"(r0), "=r"(r1), "=r"(r2), "=r"(r3) : "r"(addr));
}
__device__ __forceinline__ void mma_bf16(float* c, const uint32_t* a, const uint32_t* b) {
    asm volatile(
        "mma.sync.aligned.m16n8k16.row.col.f32.bf16.bf16.f32 "
        "{%0,%1,%2,%3}, {%4,%5,%6,%7}, {%8,%9}, {%0,%1,%2,%3};"
        : "+f"(c[0]), "+f"(c[1]), "+f"(c[2]), "+f"(c[3])
        : "r"(a[0]), "r"(a[1]), "r"(a[2]), "r"(a[3]), "r"(b[0]), "r"(b[1]));
}
__device__ __forceinline__ void cp_async16(uint32_t saddr, const void* gaddr) {
    asm volatile("cp.async.cg.shared.global [%0], [%1], 16;" :: "r"(saddr), "l"(gaddr));
}
#define CP_COMMIT() asm volatile("cp.async.commit_group;" ::: "memory")
#define CP_WAIT0()  asm volatile("cp.async.wait_group 0;" ::: "memory")

// pack two fp32 -> bf16x2 hi + residual bf16x2 lo
__device__ __forceinline__ void pack_split(float x, float y, uint32_t& hi, uint32_t& lo) {
    uint32_t h;
    asm("cvt.rn.bf16x2.f32 %0, %1, %2;" : "=r"(h) : "f"(y), "f"(x));
    float rx = x - __uint_as_float(h << 16);
    float ry = y - __uint_as_float(h & 0xffff0000u);
    uint32_t l;
    asm("cvt.rn.bf16x2.f32 %0, %1, %2;" : "=r"(l) : "f"(ry), "f"(rx));
    hi = h; lo = l;
}

// ---------------------------------------------------------------------------
// fp32 -> (hi, lo) bf16 split (for x)
// ---------------------------------------------------------------------------
__global__ void convert_split_kernel(const float* __restrict__ in,
                                     __nv_bfloat16* __restrict__ oh,
                                     __nv_bfloat16* __restrict__ ol, int n4)
{
    for (int i = blockIdx.x * blockDim.x + threadIdx.x; i < n4; i += gridDim.x * blockDim.x) {
        float4 v = *(const float4*)(in + (size_t)i * 4);
        uint32_t h0, l0, h1, l1;
        pack_split(v.x, v.y, h0, l0);
        pack_split(v.z, v.w, h1, l1);
        uint32_t* ph = (uint32_t*)(oh + (size_t)i * 4);
        uint32_t* pl = (uint32_t*)(ol + (size_t)i * 4);
        ph[0] = h0; ph[1] = h1;
        pl[0] = l0; pl[1] = l1;
    }
}

// ---------------------------------------------------------------------------
// w[K][N] fp32 -> wT hi/lo [N][K] bf16
// ---------------------------------------------------------------------------
__global__ void transpose_split_kernel(const float* __restrict__ w,
                                       __nv_bfloat16* __restrict__ th,
                                       __nv_bfloat16* __restrict__ tl,
                                       int K, int N)
{
    __shared__ float tile[32][33];
    const int tx = threadIdx.x, ty = threadIdx.y;
    const int x0 = blockIdx.x * 32;
    const int y0 = blockIdx.y * 32;
    #pragma unroll
    for (int i = 0; i < 4; i++) {
        int kl = ty + i * 8;
        tile[kl][tx] = w[(size_t)(y0 + kl) * N + x0 + tx];
    }
    __syncthreads();
    #pragma unroll
    for (int i = 0; i < 4; i++) {
        int nl = ty + i * 8;
        float v = tile[tx][nl];
        __nv_bfloat16 h = __float2bfloat16_rn(v);
        __nv_bfloat16 l = __float2bfloat16_rn(v - __bfloat162float(h));
        th[(size_t)(x0 + nl) * K + y0 + tx] = h;
        tl[(size_t)(x0 + nl) * K + y0 + tx] = l;
    }
}

// ---------------------------------------------------------------------------
// bf16-split tensor GEMM (mma.sync), CTA 128x128 BK32, 8 warps.
// Single-sync pipelined mainloop: wait0 -> sync -> issue(t+1) -> compute.
// ---------------------------------------------------------------------------
#define TILE_B   (128 * 80)
#define STAGE_B  (4 * TILE_B)

template<bool QKV_EPI>
__global__ __launch_bounds__(256)
void gemm_mma_kernel(const __nv_bfloat16* __restrict__ Ah, const __nv_bfloat16* __restrict__ Al,
                     const __nv_bfloat16* __restrict__ Bh, const __nv_bfloat16* __restrict__ Bl,
                     const float* __restrict__ bias, float* __restrict__ C,
                     __nv_bfloat16* __restrict__ qh, __nv_bfloat16* __restrict__ ql,
                     __nv_bfloat16* __restrict__ kh, __nv_bfloat16* __restrict__ kl,
                     __nv_bfloat16* __restrict__ vh, __nv_bfloat16* __restrict__ vl,
                     int M, int N, int K)
{
    extern __shared__ __align__(16) char smem[];
    const uint32_t sbase = smem_to_u32(smem);

    const int tid = threadIdx.x;
    const int lane = tid & 31;
    const int wid = tid >> 5;
    const int warp_m = wid >> 2;
    const int warp_n = wid & 3;
    const int bM = blockIdx.y * 128, bN = blockIdx.x * 128;

    const int grow = tid >> 2;
    const int gslot = tid & 3;
    const int NT = K / 32;

    auto issue = [&](int t) {
        const uint32_t sb = sbase + (t & 1) * STAGE_B;
        const int kof = t * 32 + gslot * 8;
        #pragma unroll
        for (int p = 0; p < 2; p++) {
            const int r = grow + p * 64;
            const uint32_t so = (uint32_t)(r * 80 + gslot * 16);
            cp_async16(sb + so,              Ah + (size_t)(bM + r) * K + kof);
            cp_async16(sb + TILE_B + so,     Al + (size_t)(bM + r) * K + kof);
            cp_async16(sb + 2 * TILE_B + so, Bh + (size_t)(bN + r) * K + kof);
            cp_async16(sb + 3 * TILE_B + so, Bl + (size_t)(bN + r) * K + kof);
        }
        CP_COMMIT();
    };

    float acc[4][4][4];
    #pragma unroll
    for (int i = 0; i < 4; i++)
        #pragma unroll
        for (int j = 0; j < 4; j++)
            #pragma unroll
            for (int k = 0; k < 4; k++) acc[i][j][k] = 0.f;

    issue(0);

    const int a_row = (lane & 7) + ((lane >> 3) & 1) * 8;
    const int a_sel = (lane >> 4);
    const int b_row = (lane & 7) + ((lane >> 4) << 3);
    const int b_sel = (lane >> 3) & 1;

    for (int t = 0; t < NT; t++) {
        CP_WAIT0();
        __syncthreads();
        if (t + 1 < NT) issue(t + 1);   // overlaps compute below; buffer safe past sync

        const uint32_t sb  = sbase + (t & 1) * STAGE_B;
        const uint32_t sAh = sb, sAl = sb + TILE_B, sBh = sb + 2 * TILE_B, sBl = sb + 3 * TILE_B;

        #pragma unroll
        for (int kk = 0; kk < 2; kk++) {
            uint32_t bh[8], bl[8];
            {
                const uint32_t ba = (uint32_t)((warp_n * 32 + b_row) * 80 + kk * 32 + b_sel * 16);
                ldsm_x4(bh[0], bh[1], bh[2], bh[3], sBh + ba);
                ldsm_x4(bh[4], bh[5], bh[6], bh[7], sBh + ba + 16 * 80);
                ldsm_x4(bl[0], bl[1], bl[2], bl[3], sBl + ba);
                ldsm_x4(bl[4], bl[5], bl[6], bl[7], sBl + ba + 16 * 80);
            }
            #pragma unroll
            for (int mt = 0; mt < 4; mt++) {
                const uint32_t aa = (uint32_t)((warp_m * 64 + mt * 16 + a_row) * 80
                                               + kk * 32 + a_sel * 16);
                uint32_t ah[4], al[4];
                ldsm_x4(ah[0], ah[1], ah[2], ah[3], sAh + aa);
                ldsm_x4(al[0], al[1], al[2], al[3], sAl + aa);
                #pragma unroll
                for (int nt = 0; nt < 4; nt++) {
                    mma_bf16(acc[mt][nt], ah, &bh[nt * 2]);
                    mma_bf16(acc[mt][nt], ah, &bl[nt * 2]);
                    mma_bf16(acc[mt][nt], al, &bh[nt * 2]);
                }
            }
        }
    }

    if (QKV_EPI) {
        const int tensor = bN >> 10;
        __nv_bfloat16* dh = (tensor == 0) ? qh : (tensor == 1) ? kh : vh;
        __nv_bfloat16* dl = (tensor == 0) ? ql : (tensor == 1) ? kl : vl;
        const float qscale = (tensor == 0) ? 0.125f : 1.0f;
        const int bb = bM >> 11;
        #pragma unroll
        for (int mt = 0; mt < 4; mt++) {
            const int srow = (bM & 2047) + warp_m * 64 + mt * 16 + (lane >> 2);
            #pragma unroll
            for (int nt = 0; nt < 4; nt++) {
                const int cg = bN + warp_n * 32 + nt * 8 + (lane & 3) * 2;
                const int hh = (cg & 1023) >> 6;
                const int d  = cg & 63;
                const size_t base = ((size_t)(bb * NHEAD + hh) * SEQ) * DHEAD + d;
                float v0 = (acc[mt][nt][0] + bias[cg])     * qscale;
                float v1 = (acc[mt][nt][1] + bias[cg + 1]) * qscale;
                float v2 = (acc[mt][nt][2] + bias[cg])     * qscale;
                float v3 = (acc[mt][nt][3] + bias[cg + 1]) * qscale;
                uint32_t h0, l0, h1, l1;
                pack_split(v0, v1, h0, l0);
                pack_split(v2, v3, h1, l1);
                *(uint32_t*)(dh + base + (size_t)srow * DHEAD)       = h0;
                *(uint32_t*)(dl + base + (size_t)srow * DHEAD)       = l0;
                *(uint32_t*)(dh + base + (size_t)(srow + 8) * DHEAD) = h1;
                *(uint32_t*)(dl + base + (size_t)(srow + 8) * DHEAD) = l1;
            }
        }
    } else {
        #pragma unroll
        for (int mt = 0; mt < 4; mt++) {
            const int r0 = bM + warp_m * 64 + mt * 16 + (lane >> 2);
            #pragma unroll
            for (int nt = 0; nt < 4; nt++) {
                const int c = bN + warp_n * 32 + nt * 8 + (lane & 3) * 2;
                const float bx = bias[c], by = bias[c + 1];
                *(float2*)(C + (size_t)r0 * N + c) =
                    make_float2(acc[mt][nt][0] + bx, acc[mt][nt][1] + by);
                *(float2*)(C + (size_t)(r0 + 8) * N + c) =
                    make_float2(acc[mt][nt][2] + bx, acc[mt][nt][3] + by);
            }
        }
    }
}

// ---------------------------------------------------------------------------
// Tensor-core flash attention, single-sync pipelined KV loop, Q frags hoisted.
// ---------------------------------------------------------------------------
#define FS_TILE 18432            // 128 rows * 144B

__global__ __launch_bounds__(256, 1)
void flash_mma_kernel(const __nv_bfloat16* __restrict__ qh, const __nv_bfloat16* __restrict__ ql,
                      const __nv_bfloat16* __restrict__ kh, const __nv_bfloat16* __restrict__ kl,
                      const __nv_bfloat16* __restrict__ vh, const __nv_bfloat16* __restrict__ vl,
                      __nv_bfloat16* __restrict__ ctxh, __nv_bfloat16* __restrict__ ctxl)
{
    extern __shared__ __align__(16) char smem[];
    const uint32_t sb = smem_to_u32(smem);
    const uint32_t QH = sb, QL = sb + FS_TILE;
    const int tid = threadIdx.x;
    const int lane = tid & 31;
    const int wid = tid >> 5;
    const int mrow = wid * 16;

    const int qt = blockIdx.x;
    const int bh = blockIdx.z * NHEAD + blockIdx.y;
    const int q0 = qt * 128;

    const size_t headbase = (size_t)bh * SEQ * DHEAD;

    const int gr = tid >> 1;
    const int gc = (tid & 1) * 4;
    const uint32_t gso = (uint32_t)(gr * 144 + gc * 16);

    // Q load
    {
        const __nv_bfloat16* pqh = qh + headbase + (size_t)(q0 + gr) * DHEAD + gc * 8;
        const __nv_bfloat16* pql = ql + headbase + (size_t)(q0 + gr) * DHEAD + gc * 8;
        #pragma unroll
        for (int c = 0; c < 4; c++) {
            cp_async16(QH + gso + c * 16, pqh + c * 8);
            cp_async16(QL + gso + c * 16, pql + c * 8);
        }
        CP_COMMIT();
    }

    auto loadKV = [&](int t) {
        const uint32_t bk = sb + 2 * FS_TILE + (t & 1) * 2 * FS_TILE;
        const uint32_t bv = sb + 6 * FS_TILE + (t & 1) * 2 * FS_TILE;
        const size_t g = headbase + (size_t)(t * 128 + gr) * DHEAD + gc * 8;
        #pragma unroll
        for (int c = 0; c < 4; c++) {
            cp_async16(bk + gso + c * 16,           kh + g + c * 8);
            cp_async16(bk + FS_TILE + gso + c * 16, kl + g + c * 8);
            cp_async16(bv + gso + c * 16,           vh + g + c * 8);
            cp_async16(bv + FS_TILE + gso + c * 16, vl + g + c * 8);
        }
        CP_COMMIT();
    };
    loadKV(0);

    const int arow = (lane & 7) + ((lane >> 3) & 1) * 8;
    const int asel = (lane >> 4);
    const int brow = (lane & 7) + ((lane >> 4) << 3);
    const int bsel = (lane >> 3) & 1;
    const uint32_t a_off = (uint32_t)((mrow + arow) * 144 + asel * 16);
    const uint32_t b_off = (uint32_t)(brow * 144 + bsel * 16);
    const uint32_t v_off = (uint32_t)(arow * 144 + asel * 16);

    uint32_t qfh[4][4], qfl[4][4];   // Q fragments, tile-invariant

    float m0 = -INFINITY, m1 = -INFINITY, l0 = 0.f, l1 = 0.f;
    float oacc[8][4];
    #pragma unroll
    for (int i = 0; i < 8; i++)
        #pragma unroll
        for (int j = 0; j < 4; j++) oacc[i][j] = 0.f;

    const int NTK = SEQ / 128;
    for (int t = 0; t < NTK; t++) {
        CP_WAIT0();
        __syncthreads();
        if (t + 1 < NTK) loadKV(t + 1);   // overlaps compute; buffer safe past sync

        if (t == 0) {
            #pragma unroll
            for (int ks = 0; ks < 4; ks++) {
                ldsm_x4(qfh[ks][0], qfh[ks][1], qfh[ks][2], qfh[ks][3], QH + a_off + ks * 32);
                ldsm_x4(qfl[ks][0], qfl[ks][1], qfl[ks][2], qfl[ks][3], QL + a_off + ks * 32);
            }
        }

        const uint32_t KHB = sb + 2 * FS_TILE + (t & 1) * 2 * FS_TILE;
        const uint32_t KLB = KHB + FS_TILE;
        const uint32_t VHB = sb + 6 * FS_TILE + (t & 1) * 2 * FS_TILE;
        const uint32_t VLB = VHB + FS_TILE;

        // ---- S = Q K^T ----
        float sacc[16][4];
        #pragma unroll
        for (int i = 0; i < 16; i++)
            #pragma unroll
            for (int j = 0; j < 4; j++) sacc[i][j] = 0.f;

        #pragma unroll
        for (int ks = 0; ks < 4; ks++) {
            #pragma unroll
            for (int np = 0; np < 8; np++) {
                uint32_t kbh[4], kbl[4];
                const uint32_t ko = b_off + (uint32_t)(np * 2304 + ks * 32);
                ldsm_x4(kbh[0], kbh[1], kbh[2], kbh[3], KHB + ko);
                ldsm_x4(kbl[0], kbl[1], kbl[2], kbl[3], KLB + ko);
                mma_bf16(sacc[np * 2],     qfh[ks], &kbh[0]);
                mma_bf16(sacc[np * 2],     qfh[ks], &kbl[0]);
                mma_bf16(sacc[np * 2],     qfl[ks], &kbh[0]);
                mma_bf16(sacc[np * 2 + 1], qfh[ks], &kbh[2]);
                mma_bf16(sacc[np * 2 + 1], qfh[ks], &kbl[2]);
                mma_bf16(sacc[np * 2 + 1], qfl[ks], &kbh[2]);
            }
        }

        // ---- online softmax ----
        float mx0 = -INFINITY, mx1 = -INFINITY;
        #pragma unroll
        for (int i = 0; i < 16; i++) {
            mx0 = fmaxf(mx0, fmaxf(sacc[i][0], sacc[i][1]));
            mx1 = fmaxf(mx1, fmaxf(sacc[i][2], sacc[i][3]));
        }
        mx0 = fmaxf(mx0, __shfl_xor_sync(0xffffffffu, mx0, 1));
        mx0 = fmaxf(mx0, __shfl_xor_sync(0xffffffffu, mx0, 2));
        mx1 = fmaxf(mx1, __shfl_xor_sync(0xffffffffu, mx1, 1));
        mx1 = fmaxf(mx1, __shfl_xor_sync(0xffffffffu, mx1, 2));
        const float mn0 = fmaxf(m0, mx0), mn1 = fmaxf(m1, mx1);
        const float c0 = __expf(m0 - mn0), c1 = __expf(m1 - mn1);
        m0 = mn0; m1 = mn1;

        float ps0 = 0.f, ps1 = 0.f;
        #pragma unroll
        for (int i = 0; i < 16; i++) {
            sacc[i][0] = __expf(sacc[i][0] - mn0); ps0 += sacc[i][0];
            sacc[i][1] = __expf(sacc[i][1] - mn0); ps0 += sacc[i][1];
            sacc[i][2] = __expf(sacc[i][2] - mn1); ps1 += sacc[i][2];
            sacc[i][3] = __expf(sacc[i][3] - mn1); ps1 += sacc[i][3];
        }
        ps0 += __shfl_xor_sync(0xffffffffu, ps0, 1);
        ps0 += __shfl_xor_sync(0xffffffffu, ps0, 2);
        ps1 += __shfl_xor_sync(0xffffffffu, ps1, 1);
        ps1 += __shfl_xor_sync(0xffffffffu, ps1, 2);
        l0 = l0 * c0 + ps0;
        l1 = l1 * c1 + ps1;

        #pragma unroll
        for (int i = 0; i < 8; i++) {
            oacc[i][0] *= c0; oacc[i][1] *= c0;
            oacc[i][2] *= c1; oacc[i][3] *= c1;
        }

        // ---- O += P V ----
        #pragma unroll
        for (int ks = 0; ks < 8; ks++) {
            uint32_t ah[4], al[4];
            pack_split(sacc[2 * ks][0],     sacc[2 * ks][1],     ah[0], al[0]);
            pack_split(sacc[2 * ks][2],     sacc[2 * ks][3],     ah[1], al[1]);
            pack_split(sacc[2 * ks + 1][0], sacc[2 * ks + 1][1], ah[2], al[2]);
            pack_split(sacc[2 * ks + 1][2], sacc[2 * ks + 1][3], ah[3], al[3]);
            #pragma unroll
            for (int nt = 0; nt < 4; nt++) {
                uint32_t vbh[4], vbl[4];
                const uint32_t vo = v_off + (uint32_t)(ks * 2304 + nt * 32);
                ldsm_x4t(vbh[0], vbh[1], vbh[2], vbh[3], VHB + vo);
                ldsm_x4t(vbl[0], vbl[1], vbl[2], vbl[3], VLB + vo);
                mma_bf16(oacc[nt * 2],     ah, &vbh[0]);
                mma_bf16(oacc[nt * 2],     ah, &vbl[0]);
                mma_bf16(oacc[nt * 2],     al, &vbh[0]);
                mma_bf16(oacc[nt * 2 + 1], ah, &vbh[2]);
                mma_bf16(oacc[nt * 2 + 1], ah, &vbl[2]);
                mma_bf16(oacc[nt * 2 + 1], al, &vbh[2]);
            }
        }
    }

    // ---- epilogue ----
    const float inv0 = 1.f / l0, inv1 = 1.f / l1;
    const int row0 = q0 + mrow + (lane >> 2);
    const size_t base0 = ((size_t)blockIdx.z * SEQ + row0) * DMODEL
                         + blockIdx.y * DHEAD + (lane & 3) * 2;
    const size_t base1 = base0 + 8 * DMODEL;
    #pragma unroll
    for (int nt = 0; nt < 8; nt++) {
        uint32_t h, l;
        pack_split(oacc[nt][0] * inv0, oacc[nt][1] * inv0, h, l);
        *(uint32_t*)(ctxh + base0 + nt * 8) = h;
        *(uint32_t*)(ctxl + base0 + nt * 8) = l;
        pack_split(oacc[nt][2] * inv1, oacc[nt][3] * inv1, h, l);
        *(uint32_t*)(ctxh + base1 + nt * 8) = h;
        *(uint32_t*)(ctxl + base1 + nt * 8) = l;
    }
}

// ---------------------------------------------------------------------------
extern "C" void kernel_launch(void* const* d_in, const int* in_sizes, int n_in,
                              void* d_out, int out_size)
{
    const float* x      = (const float*)d_in[0];
    const float* w_qkv  = (const float*)d_in[1];
    const float* b_qkv  = (const float*)d_in[2];
    const float* w_out  = (const float*)d_in[3];
    const float* b_out  = (const float*)d_in[4];
    float* out = (float*)d_out;

    __nv_bfloat16 *xh, *xl, *wqh, *wql, *woh, *wol;
    __nv_bfloat16 *qh, *ql, *kh, *kl, *vh, *vl, *ch, *cl;
    cudaGetSymbolAddress((void**)&xh, g_xh);
    cudaGetSymbolAddress((void**)&xl, g_xl);
    cudaGetSymbolAddress((void**)&wqh, g_wqkvT_h);
    cudaGetSymbolAddress((void**)&wql, g_wqkvT_l);
    cudaGetSymbolAddress((void**)&woh, g_woutT_h);
    cudaGetSymbolAddress((void**)&wol, g_woutT_l);
    cudaGetSymbolAddress((void**)&qh, g_qh);
    cudaGetSymbolAddress((void**)&ql, g_ql);
    cudaGetSymbolAddress((void**)&kh, g_kh);
    cudaGetSymbolAddress((void**)&kl, g_kl);
    cudaGetSymbolAddress((void**)&vh, g_vh);
    cudaGetSymbolAddress((void**)&vl, g_vl);
    cudaGetSymbolAddress((void**)&ch, g_ctxh);
    cudaGetSymbolAddress((void**)&cl, g_ctxl);

    const int GEMM_SMEM  = 2 * STAGE_B;     // 81920
    const int FLASH_SMEM = 10 * FS_TILE;    // 184320
    cudaFuncSetAttribute(gemm_mma_kernel<true>,
                         cudaFuncAttributeMaxDynamicSharedMemorySize, GEMM_SMEM);
    cudaFuncSetAttribute(gemm_mma_kernel<false>,
                         cudaFuncAttributeMaxDynamicSharedMemorySize, GEMM_SMEM);
    cudaFuncSetAttribute(flash_mma_kernel,
                         cudaFuncAttributeMaxDynamicSharedMemorySize, FLASH_SMEM);

    // 0) conversions
    convert_split_kernel<<<2048, 256>>>(x, xh, xl, MTOT * DMODEL / 4);
    transpose_split_kernel<<<dim3(N_QKV / 32, DMODEL / 32), dim3(32, 8)>>>(
        w_qkv, wqh, wql, DMODEL, N_QKV);
    transpose_split_kernel<<<dim3(DMODEL / 32, DMODEL / 32), dim3(32, 8)>>>(
        w_out, woh, wol, DMODEL, DMODEL);

    // 1) QKV projection -> q/k/v head-major bf16 hi/lo (q pre-scaled)
    {
        dim3 grid(N_QKV / 128, MTOT / 128);
        gemm_mma_kernel<true><<<grid, 256, GEMM_SMEM>>>(
            xh, xl, wqh, wql, b_qkv, nullptr,
            qh, ql, kh, kl, vh, vl, MTOT, N_QKV, DMODEL);
    }
    // 2) Tensor-core flash attention -> ctx hi/lo
    {
        dim3 grid(SEQ / 128, NHEAD, BATCH);
        flash_mma_kernel<<<grid, 256, FLASH_SMEM>>>(qh, ql, kh, kl, vh, vl, ch, cl);
    }
    // 3) Output projection -> fp32 out
    {
        dim3 grid(DMODEL / 128, MTOT / 128);
        gemm_mma_kernel<false><<<grid, 256, GEMM_SMEM>>>(
            ch, cl, woh, wol, b_out, out,
            nullptr, nullptr, nullptr, nullptr, nullptr, nullptr,
            MTOT, DMODEL, DMODEL);
    }
}